// round 13
// baseline (speedup 1.0000x reference)
#include <cuda_runtime.h>
#include <cuda_fp16.h>
#include <math.h>
#include <stdint.h>

typedef unsigned long long u64;

// ---------------- problem constants ----------------
// B=4, C=128, H=W=512, P=16, GH=GW=32, N=1024, PATCH_DIM=32768, DIM=512,
// MLP=256, DH=64, HEADS=(2,4,8), NUM_REL=3969

// ---------------- scratch (device globals) ----------------
__device__ __align__(16) __half g_pw2h[32768 * 512]; // patch_w fp16 [d][k']
__device__ __align__(16) float  g_x[4096 * 512];     // residual stream (fp32)
__device__ __align__(16) float  g_attn[4194304];     // patch split-K partials
__device__ __align__(16) __half g_xnh[4096 * 512];   // LN output fp16
__device__ __align__(16) __half g_qkvh[4096 * 1536]; // qkv fp16
__device__ __align__(16) __half g_oh[4096 * 512];    // attention out fp16
__device__ __align__(16) __half g_hh[4096 * 256];    // FFN hidden fp16
__device__ __align__(16) __half g_wtsh[2621440];     // fp16 weights [n][K]

#define HBUF_XN  0
#define HBUF_QKV 1
#define HBUF_O   2
#define HBUF_H   3
__device__ __forceinline__ __half* bufh(int id) {
    switch (id) {
        case HBUF_XN:  return g_xnh;
        case HBUF_QKV: return g_qkvh;
        case HBUF_O:   return g_oh;
        default:       return g_hh;
    }
}

// ============================================================================
__global__ void k_zero(float* o, int n) {
    int i = blockIdx.x * blockDim.x + threadIdx.x;
    if (i < n) o[i] = 0.0f;
}

// ============================================================================
// helpers
// ============================================================================
__device__ __forceinline__ uint32_t f2tf(float f) {
    uint32_t r;
    asm("cvt.rna.tf32.f32 %0, %1;" : "=r"(r) : "f"(f));
    return r;
}
__device__ __forceinline__ void mma8(float* c, const uint32_t* a,
                                     uint32_t b0, uint32_t b1) {
    asm("mma.sync.aligned.m16n8k8.row.col.f32.tf32.tf32.f32 "
        "{%0,%1,%2,%3},{%4,%5,%6,%7},{%8,%9},{%0,%1,%2,%3};"
        : "+f"(c[0]), "+f"(c[1]), "+f"(c[2]), "+f"(c[3])
        : "r"(a[0]), "r"(a[1]), "r"(a[2]), "r"(a[3]), "r"(b0), "r"(b1));
}
__device__ __forceinline__ void mma16(float* c, const uint32_t* a,
                                      uint32_t b0, uint32_t b1) {
    asm("mma.sync.aligned.m16n8k16.row.col.f32.f16.f16.f32 "
        "{%0,%1,%2,%3},{%4,%5,%6,%7},{%8,%9},{%0,%1,%2,%3};"
        : "+f"(c[0]), "+f"(c[1]), "+f"(c[2]), "+f"(c[3])
        : "r"(a[0]), "r"(a[1]), "r"(a[2]), "r"(a[3]), "r"(b0), "r"(b1));
}
__device__ __forceinline__ uint32_t ldu(const float* p) {
    return __float_as_uint(*p);
}
__device__ __forceinline__ uint32_t smem_u32(const void* p) {
    return (uint32_t)__cvta_generic_to_shared(p);
}
__device__ __forceinline__ void cpa16(uint32_t s, const void* g) {
    asm volatile("cp.async.cg.shared.global [%0], [%1], 16;" :: "r"(s), "l"(g));
}
__device__ __forceinline__ void cpcommit() {
    asm volatile("cp.async.commit_group;");
}
__device__ __forceinline__ void cpwait0() {
    asm volatile("cp.async.wait_group 0;" ::: "memory");
}

// ============================================================================
// permute patch_w to fp16 [d][k']
// ============================================================================
__global__ void k_permute_pw(const float* __restrict__ pw) {
    int idx = blockIdx.x * blockDim.x + threadIdx.x;   // 4096 * 512
    if (idx >= 4096 * 512) return;
    int k8 = idx >> 9;
    int d  = idx & 511;
    int kp = k8 * 8;
    int c  = kp >> 8;
    int p  = kp & 255;
    __half2 h[4];
#pragma unroll
    for (int i = 0; i < 4; i++) {
        float v0 = pw[(size_t)((p + 2 * i) * 128 + c) * 512 + d];
        float v1 = pw[(size_t)((p + 2 * i + 1) * 128 + c) * 512 + d];
        h[i] = __floats2half2_rn(v0, v1);
    }
    uint4 u;
    u.x = *(uint32_t*)&h[0]; u.y = *(uint32_t*)&h[1];
    u.z = *(uint32_t*)&h[2]; u.w = *(uint32_t*)&h[3];
    *(uint4*)&g_pw2h[(size_t)d * 32768 + kp] = u;
}

// ============================================================================
// transpose weight [K][N] -> g_wtsh[dstOff + n*K + k] (fp16, one-time)
// ============================================================================
__global__ void k_cvt_t(const float* __restrict__ src, u64 dstOff, int K, int N) {
    int idx = blockIdx.x * blockDim.x + threadIdx.x;   // (K/8) * N
    if (idx >= (K >> 3) * N) return;
    int n  = idx % N;
    int k8 = idx / N;
    int k  = k8 * 8;
    __half2 h[4];
#pragma unroll
    for (int i = 0; i < 4; i++) {
        float v0 = src[(size_t)(k + 2 * i) * N + n];
        float v1 = src[(size_t)(k + 2 * i + 1) * N + n];
        h[i] = __floats2half2_rn(v0, v1);
    }
    uint4 u;
    u.x = *(uint32_t*)&h[0]; u.y = *(uint32_t*)&h[1];
    u.z = *(uint32_t*)&h[2]; u.w = *(uint32_t*)&h[3];
    *(uint4*)&g_wtsh[dstOff + (size_t)n * K + k] = u;
}

// ============================================================================
// patch embed GEMM (fp16 m16n8k16) — unchanged R12 (validated)
// ============================================================================
__global__ __launch_bounds__(256, 1)
void k_patch_h(const float* __restrict__ img) {
    extern __shared__ char smc[];
    char* Ab0 = smc;                 // 2 x 256*64 = 32768 B
    char* Bb0 = smc + 32768;         // 2 x 128*64 = 16384 B

    const int tid  = threadIdx.x;
    const int lane = tid & 31;
    const int wid  = tid >> 5;
    const int warp_m = (wid & 3) * 64;
    const int warp_n = (wid >> 2) * 64;
    const int m0 = blockIdx.y * 256;
    const int n0 = blockIdx.x * 128;
    const int kHalf = blockIdx.z;
    const int kBase = kHalf * 16384;

    const int kg = tid & 3;
    const int am = tid >> 2;
    const float* abase[4];
#pragma unroll
    for (int t = 0; t < 4; t++) {
        int m_g = m0 + am + t * 64;
        int bb  = m_g >> 10;
        int tok = m_g & 1023;
        int gh = tok >> 5, gw = tok & 31;
        abase[t] = img + (size_t)bb * 33554432 + (size_t)(gh * 16) * 512 + gw * 16;
    }
    const int bn = tid >> 2;
    const __half* bbase[2];
#pragma unroll
    for (int t = 0; t < 2; t++)
        bbase[t] = g_pw2h + (size_t)(n0 + bn + t * 64) * 32768 + kg * 8;

    const int aSw = (kg ^ ((am >> 1) & 3)) << 4;
    const int bSw = (kg ^ ((bn >> 1) & 3)) << 4;
    int aSt[4], bSt[2];
#pragma unroll
    for (int t = 0; t < 4; t++) aSt[t] = (am + 64 * t) * 64 + aSw;
#pragma unroll
    for (int t = 0; t < 2; t++) bSt[t] = (bn + 64 * t) * 64 + bSw;

    const int kb4 = (lane & 3) * 4;

    float c[4][8][4];
#pragma unroll
    for (int i = 0; i < 4; i++)
#pragma unroll
        for (int j = 0; j < 8; j++)
#pragma unroll
            for (int q = 0; q < 4; q++) c[i][j][q] = 0.0f;

    float4 pa[4][2];

    {
        int k = kBase + kg * 8;
        int cc = k >> 8, rem = k & 255;
        const size_t aoff = (size_t)cc * 262144 + (rem >> 4) * 512 + (rem & 15);
#pragma unroll
        for (int t = 0; t < 4; t++) {
            pa[t][0] = *(const float4*)(abase[t] + aoff);
            pa[t][1] = *(const float4*)(abase[t] + aoff + 4);
        }
#pragma unroll
        for (int t = 0; t < 2; t++)
            cpa16(smem_u32(Bb0 + bSt[t]), bbase[t] + kBase);
        cpcommit();
#pragma unroll
        for (int t = 0; t < 4; t++) {
            __half2 h0 = __floats2half2_rn(pa[t][0].x, pa[t][0].y);
            __half2 h1 = __floats2half2_rn(pa[t][0].z, pa[t][0].w);
            __half2 h2 = __floats2half2_rn(pa[t][1].x, pa[t][1].y);
            __half2 h3 = __floats2half2_rn(pa[t][1].z, pa[t][1].w);
            uint4 u;
            u.x = *(uint32_t*)&h0; u.y = *(uint32_t*)&h1;
            u.z = *(uint32_t*)&h2; u.w = *(uint32_t*)&h3;
            *(uint4*)(Ab0 + aSt[t]) = u;
        }
    }

    for (int it = 0; it < 512; it++) {
        if (it < 511) {
            int k = kBase + (it + 1) * 32 + kg * 8;
            int cc = k >> 8, rem = k & 255;
            const size_t aoff = (size_t)cc * 262144 + (rem >> 4) * 512 + (rem & 15);
#pragma unroll
            for (int t = 0; t < 4; t++) {
                pa[t][0] = *(const float4*)(abase[t] + aoff);
                pa[t][1] = *(const float4*)(abase[t] + aoff + 4);
            }
        }
        cpwait0();
        __syncthreads();
        const int bsel = it & 1;
        const int nsel = bsel ^ 1;
        if (it < 511) {
            int kNext = kBase + (it + 1) * 32;
#pragma unroll
            for (int t = 0; t < 2; t++)
                cpa16(smem_u32(Bb0 + nsel * 8192 + bSt[t]), bbase[t] + kNext);
            cpcommit();
        }

        const char* Asb = Ab0 + bsel * 16384;
        const char* Bsb = Bb0 + bsel * 8192;
#pragma unroll
        for (int s = 0; s < 2; s++) {
            const int gl0 = s * 2, gl1 = s * 2 + 1;
            uint32_t af[4][4];
#pragma unroll
            for (int ma = 0; ma < 4; ma++) {
                int r0 = warp_m + ma * 16 + (lane >> 2);
                int r1 = r0 + 8;
                int x0 = (r0 >> 1) & 3, x1 = (r1 >> 1) & 3;
                af[ma][0] = *(const uint32_t*)(Asb + r0 * 64 + ((gl0 ^ x0) << 4) + kb4);
                af[ma][1] = *(const uint32_t*)(Asb + r1 * 64 + ((gl0 ^ x1) << 4) + kb4);
                af[ma][2] = *(const uint32_t*)(Asb + r0 * 64 + ((gl1 ^ x0) << 4) + kb4);
                af[ma][3] = *(const uint32_t*)(Asb + r1 * 64 + ((gl1 ^ x1) << 4) + kb4);
            }
#pragma unroll
            for (int na = 0; na < 8; na++) {
                int n = warp_n + na * 8 + (lane >> 2);
                int xn = (n >> 1) & 3;
                uint32_t b0 = *(const uint32_t*)(Bsb + n * 64 + ((gl0 ^ xn) << 4) + kb4);
                uint32_t b1 = *(const uint32_t*)(Bsb + n * 64 + ((gl1 ^ xn) << 4) + kb4);
#pragma unroll
                for (int ma = 0; ma < 4; ma++)
                    mma16(c[ma][na], af[ma], b0, b1);
            }
        }

        if (it < 511) {
#pragma unroll
            for (int t = 0; t < 4; t++) {
                __half2 h0 = __floats2half2_rn(pa[t][0].x, pa[t][0].y);
                __half2 h1 = __floats2half2_rn(pa[t][0].z, pa[t][0].w);
                __half2 h2 = __floats2half2_rn(pa[t][1].x, pa[t][1].y);
                __half2 h3 = __floats2half2_rn(pa[t][1].z, pa[t][1].w);
                uint4 u;
                u.x = *(uint32_t*)&h0; u.y = *(uint32_t*)&h1;
                u.z = *(uint32_t*)&h2; u.w = *(uint32_t*)&h3;
                *(uint4*)(Ab0 + nsel * 16384 + aSt[t]) = u;
            }
        }
    }

    float* part = g_attn + (size_t)kHalf * 2097152;
#pragma unroll
    for (int ma = 0; ma < 4; ma++) {
        int r0 = m0 + warp_m + ma * 16 + (lane >> 2);
        int r1 = r0 + 8;
#pragma unroll
        for (int na = 0; na < 8; na++) {
            int col = n0 + warp_n + na * 8 + (lane & 3) * 2;
            *(float2*)(part + (size_t)r0 * 512 + col) = make_float2(c[ma][na][0], c[ma][na][1]);
            *(float2*)(part + (size_t)r1 * 512 + col) = make_float2(c[ma][na][2], c[ma][na][3]);
        }
    }
}

// ============================================================================
// combine split-K partials:  g_x = p0 + p1 + patch_b + pos_emb  (fp32)
// ============================================================================
__global__ void k_patch_sum(const float* __restrict__ pb,
                            const float* __restrict__ pos) {
    int idx = blockIdx.x * blockDim.x + threadIdx.x;
    if (idx >= 4096 * 128) return;
    int row = idx >> 7;
    int c4  = idx & 127;
    int tok = row & 1023;
    float4 a = ((const float4*)g_attn)[idx];
    float4 b = ((const float4*)(g_attn + 2097152))[idx];
    float4 pb4 = ((const float4*)pb)[c4];
    float4 ps  = ((const float4*)pos)[(size_t)tok * 128 + c4];
    float4 o;
    o.x = a.x + b.x + pb4.x + ps.x;
    o.y = a.y + b.y + pb4.y + ps.y;
    o.z = a.z + b.z + pb4.z + ps.z;
    o.w = a.w + b.w + pb4.w + ps.w;
    ((float4*)g_x)[idx] = o;
}

// ============================================================================
// layer GEMM fp16: C = A(half[M][K]) @ W(half[n][K]) (+bias)(+gelu)
// out: fp16 buffer OR fp32 g_x with residual.
// CTA 128x128, 512 thr, warp 32x32, BK=32, cp.async double-buffered.
// ============================================================================
__global__ __launch_bounds__(512, 1)
void k_gemm_h(int aId, int K, u64 bOff,
              int cHalfId, int ldC,
              const float* __restrict__ bias, int addResid, int gelu) {
    __shared__ __align__(16) char Ab[2][8192];
    __shared__ __align__(16) char Bb[2][8192];

    const int tid  = threadIdx.x;
    const int lane = tid & 31;
    const int wid  = tid >> 5;
    const int warp_m = (wid & 3) * 32;
    const int warp_n = (wid >> 2) * 32;
    const int m0 = blockIdx.y * 128;
    const int n0 = blockIdx.x * 128;

    const __half* A = bufh(aId);
    const __half* Bw = g_wtsh + bOff;

    const int kg = tid & 3;
    const int row = tid >> 2;          // 0..127
    const int sw = (kg ^ ((row >> 1) & 3)) << 4;
    const int stOff = row * 64 + sw;

    const __half* aSrc = A + (size_t)(m0 + row) * K + kg * 8;
    const __half* bSrc = Bw + (size_t)(n0 + row) * K + kg * 8;

    const int kb4 = (lane & 3) * 4;

    float c[2][4][4];
#pragma unroll
    for (int i = 0; i < 2; i++)
#pragma unroll
        for (int j = 0; j < 4; j++)
#pragma unroll
            for (int q = 0; q < 4; q++) c[i][j][q] = 0.0f;

    // prologue
    cpa16(smem_u32(Ab[0] + stOff), aSrc);
    cpa16(smem_u32(Bb[0] + stOff), bSrc);
    cpcommit();

    const int iters = K >> 5;
    for (int it = 0; it < iters; it++) {
        cpwait0();
        __syncthreads();
        const int bsel = it & 1;
        const int nsel = bsel ^ 1;
        if (it < iters - 1) {
            int k0 = (it + 1) * 32;
            cpa16(smem_u32(Ab[nsel] + stOff), aSrc + k0);
            cpa16(smem_u32(Bb[nsel] + stOff), bSrc + k0);
            cpcommit();
        }

        const char* Asb = Ab[bsel];
        const char* Bsb = Bb[bsel];
#pragma unroll
        for (int s = 0; s < 2; s++) {
            const int gl0 = s * 2, gl1 = s * 2 + 1;
            uint32_t af[2][4];
#pragma unroll
            for (int ma = 0; ma < 2; ma++) {
                int r0 = warp_m + ma * 16 + (lane >> 2);
                int r1 = r0 + 8;
                int x0 = (r0 >> 1) & 3, x1 = (r1 >> 1) & 3;
                af[ma][0] = *(const uint32_t*)(Asb + r0 * 64 + ((gl0 ^ x0) << 4) + kb4);
                af[ma][1] = *(const uint32_t*)(Asb + r1 * 64 + ((gl0 ^ x1) << 4) + kb4);
                af[ma][2] = *(const uint32_t*)(Asb + r0 * 64 + ((gl1 ^ x0) << 4) + kb4);
                af[ma][3] = *(const uint32_t*)(Asb + r1 * 64 + ((gl1 ^ x1) << 4) + kb4);
            }
#pragma unroll
            for (int na = 0; na < 4; na++) {
                int n = warp_n + na * 8 + (lane >> 2);
                int xn = (n >> 1) & 3;
                uint32_t b0 = *(const uint32_t*)(Bsb + n * 64 + ((gl0 ^ xn) << 4) + kb4);
                uint32_t b1 = *(const uint32_t*)(Bsb + n * 64 + ((gl1 ^ xn) << 4) + kb4);
#pragma unroll
                for (int ma = 0; ma < 2; ma++)
                    mma16(c[ma][na], af[ma], b0, b1);
            }
        }
    }

    // epilogue
#pragma unroll
    for (int ma = 0; ma < 2; ma++) {
        int r0 = m0 + warp_m + ma * 16 + (lane >> 2);
        int r1 = r0 + 8;
#pragma unroll
        for (int na = 0; na < 4; na++) {
            int col = n0 + warp_n + na * 8 + (lane & 3) * 2;
            float v[4] = {c[ma][na][0], c[ma][na][1], c[ma][na][2], c[ma][na][3]};
            if (bias) {
                float b0 = bias[col], b1 = bias[col + 1];
                v[0] += b0; v[1] += b1; v[2] += b0; v[3] += b1;
            }
            if (gelu) {
#pragma unroll
                for (int q = 0; q < 4; q++)
                    v[q] = 0.5f * v[q] * (1.0f + erff(v[q] * 0.70710678118654752f));
            }
            if (cHalfId >= 0) {
                __half* Ch = bufh(cHalfId);
                __half2 h0 = __floats2half2_rn(v[0], v[1]);
                __half2 h1 = __floats2half2_rn(v[2], v[3]);
                *(uint32_t*)(Ch + (size_t)r0 * ldC + col) = *(uint32_t*)&h0;
                *(uint32_t*)(Ch + (size_t)r1 * ldC + col) = *(uint32_t*)&h1;
            } else {
                if (addResid) {
                    v[0] += g_x[(size_t)r0 * 512 + col];
                    v[1] += g_x[(size_t)r0 * 512 + col + 1];
                    v[2] += g_x[(size_t)r1 * 512 + col];
                    v[3] += g_x[(size_t)r1 * 512 + col + 1];
                }
                *(float2*)(g_x + (size_t)r0 * 512 + col) = make_float2(v[0], v[1]);
                *(float2*)(g_x + (size_t)r1 * 512 + col) = make_float2(v[2], v[3]);
            }
        }
    }
}

// ============================================================================
// FUSED attention: S = QK^T in fp16 (mma16), softmax fp32, P@V in tf32.
// Q/K tiles: fp16 [row][64] (128B rows, granule swizzle g^(row&7)).
// ============================================================================
__global__ __launch_bounds__(256, 1)
void k_attn_fused(const float* __restrict__ tbl, int qkvld, int inner, int hc) {
    extern __shared__ char smc[];
    char*  Qs = smc;                       // 128*128B = 16384
    char*  Ks = smc + 16384;               // 128*128B = 16384
    float* Vs = (float*)(smc + 32768);     // 128*72*4 = 36864
    float* Ps = (float*)(smc + 32768 + 36864); // 128*128*4 = 65536

    const int tid  = threadIdx.x;
    const int lane = tid & 31;
    const int wid  = tid >> 5;
    const int i0 = blockIdx.x * 128;
    const int z  = blockIdx.y;
    const int bb = z / hc, head = z % hc;
    const __half* Qbh = g_qkvh + (size_t)bb * 1024 * qkvld + head * 64;
    const __half* Kbh = Qbh + inner;
    const __half* Vbh = Qbh + 2 * inner;

    // ---- load Q tile once (fp16): g = granule 0..7, row = tid>>3 (+32t) ----
    {
        const int g = tid & 7;
        const int rw = tid >> 3;
#pragma unroll
        for (int t = 0; t < 4; t++) {
            int m = rw + t * 32;
            uint4 v = *(const uint4*)(Qbh + (size_t)(i0 + m) * qkvld + g * 8);
            *(uint4*)(Qs + m * 128 + ((g ^ (m & 7)) << 4)) = v;
        }
    }

    const int rl0 = wid * 16 + (lane >> 2);
    const int rl1 = rl0 + 8;
    const int gr0 = i0 + rl0, gr1 = i0 + rl1;
    const int ih0 = gr0 >> 5, iw0 = gr0 & 31;
    const int ih1 = gr1 >> 5, iw1 = gr1 & 31;
    const int kb  = lane & 3;
    const int kb4 = kb * 4;
    const int x0 = rl0 & 7;   // same as rl1&7

    float o[8][4];
#pragma unroll
    for (int j = 0; j < 8; j++) { o[j][0] = o[j][1] = o[j][2] = o[j][3] = 0.f; }
    float m0 = -1e30f, m1 = -1e30f, l0 = 0.f, l1 = 0.f;

    for (int jt = 0; jt < 8; jt++) {
        const int j0 = jt * 128;
        __syncthreads();
        // ---- load K tile fp16 [j][64] ----
        {
            const int g = tid & 7;
            const int rw = tid >> 3;
#pragma unroll
            for (int t = 0; t < 4; t++) {
                int m = rw + t * 32;
                uint4 v = *(const uint4*)(Kbh + (size_t)(j0 + m) * qkvld + g * 8);
                *(uint4*)(Ks + m * 128 + ((g ^ (m & 7)) << 4)) = v;
            }
        }
        // ---- load V tile, cvt to fp32 [j][72] ----
        {
            const int c8 = tid & 7;
            const int rw = tid >> 3;
#pragma unroll
            for (int t = 0; t < 4; t++) {
                int j = rw + t * 32;
                uint4 u = *(const uint4*)(Vbh + (size_t)(j0 + j) * qkvld + c8 * 8);
                __half2* hp = (__half2*)&u;
                float* dst = Vs + j * 72 + c8 * 8;
#pragma unroll
                for (int q = 0; q < 4; q++) {
                    float2 f = __half22float2(hp[q]);
                    dst[2 * q] = f.x; dst[2 * q + 1] = f.y;
                }
            }
        }
        __syncthreads();

        // ---- S = Q K^T (fp16, K=64: 4 k-steps of 16) ----
        float s[16][4];
#pragma unroll
        for (int na = 0; na < 16; na++) { s[na][0] = s[na][1] = s[na][2] = s[na][3] = 0.f; }
#pragma unroll
        for (int kk = 0; kk < 4; kk++) {
            const int gl0 = kk * 2, gl1 = kk * 2 + 1;
            uint32_t af[4];
            af[0] = *(const uint32_t*)(Qs + rl0 * 128 + ((gl0 ^ x0) << 4) + kb4);
            af[1] = *(const uint32_t*)(Qs + rl1 * 128 + ((gl0 ^ x0) << 4) + kb4);
            af[2] = *(const uint32_t*)(Qs + rl0 * 128 + ((gl1 ^ x0) << 4) + kb4);
            af[3] = *(const uint32_t*)(Qs + rl1 * 128 + ((gl1 ^ x0) << 4) + kb4);
#pragma unroll
            for (int na = 0; na < 16; na++) {
                int n = na * 8 + (lane >> 2);
                int xn = n & 7;
                uint32_t b0 = *(const uint32_t*)(Ks + n * 128 + ((gl0 ^ xn) << 4) + kb4);
                uint32_t b1 = *(const uint32_t*)(Ks + n * 128 + ((gl1 ^ xn) << 4) + kb4);
                mma16(s[na], af, b0, b1);
            }
        }
        // ---- scale + rel bias ----
#pragma unroll
        for (int na = 0; na < 16; na++) {
            int jj = j0 + na * 8 + (lane & 3) * 2;
            int jh0 = jj >> 5, jw0 = jj & 31;
            int jh1 = (jj + 1) >> 5, jw1 = (jj + 1) & 31;
            s[na][0] = s[na][0] * 0.125f + tbl[(size_t)((ih0 - jh0 + 31) * 63 + (iw0 - jw0 + 31)) * hc + head];
            s[na][1] = s[na][1] * 0.125f + tbl[(size_t)((ih0 - jh1 + 31) * 63 + (iw0 - jw1 + 31)) * hc + head];
            s[na][2] = s[na][2] * 0.125f + tbl[(size_t)((ih1 - jh0 + 31) * 63 + (iw1 - jw0 + 31)) * hc + head];
            s[na][3] = s[na][3] * 0.125f + tbl[(size_t)((ih1 - jh1 + 31) * 63 + (iw1 - jw1 + 31)) * hc + head];
        }
        // ---- online softmax ----
        float mx0 = -1e30f, mx1 = -1e30f;
#pragma unroll
        for (int na = 0; na < 16; na++) {
            mx0 = fmaxf(mx0, fmaxf(s[na][0], s[na][1]));
            mx1 = fmaxf(mx1, fmaxf(s[na][2], s[na][3]));
        }
        mx0 = fmaxf(mx0, __shfl_xor_sync(0xffffffffu, mx0, 1));
        mx0 = fmaxf(mx0, __shfl_xor_sync(0xffffffffu, mx0, 2));
        mx1 = fmaxf(mx1, __shfl_xor_sync(0xffffffffu, mx1, 1));
        mx1 = fmaxf(mx1, __shfl_xor_sync(0xffffffffu, mx1, 2));
        float mn0 = fmaxf(m0, mx0), mn1 = fmaxf(m1, mx1);
        float al0 = __expf(m0 - mn0), al1 = __expf(m1 - mn1);
        float ls0 = 0.f, ls1 = 0.f;
#pragma unroll
        for (int na = 0; na < 16; na++) {
            s[na][0] = __expf(s[na][0] - mn0);
            s[na][1] = __expf(s[na][1] - mn0);
            s[na][2] = __expf(s[na][2] - mn1);
            s[na][3] = __expf(s[na][3] - mn1);
            ls0 += s[na][0] + s[na][1];
            ls1 += s[na][2] + s[na][3];
        }
        ls0 += __shfl_xor_sync(0xffffffffu, ls0, 1);
        ls0 += __shfl_xor_sync(0xffffffffu, ls0, 2);
        ls1 += __shfl_xor_sync(0xffffffffu, ls1, 1);
        ls1 += __shfl_xor_sync(0xffffffffu, ls1, 2);
        l0 = l0 * al0 + ls0;
        l1 = l1 * al1 + ls1;
        m0 = mn0; m1 = mn1;
#pragma unroll
        for (int j = 0; j < 8; j++) {
            o[j][0] *= al0; o[j][1] *= al0; o[j][2] *= al1; o[j][3] *= al1;
        }
        // ---- store P to smem (tf32 bits, granule swizzle) ----
#pragma unroll
        for (int na = 0; na < 16; na++) {
            int c = na * 8 + (lane & 3) * 2;
            int g = c >> 2;
            int a0 = rl0 * 128 + ((g ^ (rl0 & 7)) << 2) + (c & 3);
            int a1 = rl1 * 128 + ((g ^ (rl1 & 7)) << 2) + (c & 3);
            Ps[a0]     = __uint_as_float(f2tf(s[na][0]));
            Ps[a0 + 1] = __uint_as_float(f2tf(s[na][1]));
            Ps[a1]     = __uint_as_float(f2tf(s[na][2]));
            Ps[a1 + 1] = __uint_as_float(f2tf(s[na][3]));
        }
        __syncthreads();
        // ---- O += P @ V (tf32, K=128) ----
#pragma unroll
        for (int kk = 0; kk < 16; kk++) {
            uint32_t af[4];
            int g0 = kk * 2, g1 = kk * 2 + 1;
            af[0] = ldu(&Ps[rl0 * 128 + ((g0 ^ (rl0 & 7)) << 2) + kb]);
            af[1] = ldu(&Ps[rl1 * 128 + ((g0 ^ (rl1 & 7)) << 2) + kb]);
            af[2] = ldu(&Ps[rl0 * 128 + ((g1 ^ (rl0 & 7)) << 2) + kb]);
            af[3] = ldu(&Ps[rl1 * 128 + ((g1 ^ (rl1 & 7)) << 2) + kb]);
#pragma unroll
            for (int na = 0; na < 8; na++) {
                int n = na * 8 + (lane >> 2);
                uint32_t b0 = ldu(&Vs[(kk * 8 + kb) * 72 + n]);
                uint32_t b1 = ldu(&Vs[(kk * 8 + 4 + kb) * 72 + n]);
                mma8(o[na], af, b0, b1);
            }
        }
    }

    // ---- finalize: O / l -> g_oh (fp16) ----
    float inv0 = 1.0f / l0, inv1 = 1.0f / l1;
    __half* Obh = g_oh + ((size_t)bb * 1024) * inner + head * 64;
#pragma unroll
    for (int na = 0; na < 8; na++) {
        int col = na * 8 + (lane & 3) * 2;
        __half2 w0 = __floats2half2_rn(o[na][0] * inv0, o[na][1] * inv0);
        __half2 w1 = __floats2half2_rn(o[na][2] * inv1, o[na][3] * inv1);
        *(uint32_t*)(Obh + (size_t)gr0 * inner + col) = *(uint32_t*)&w0;
        *(uint32_t*)(Obh + (size_t)gr1 * inner + col) = *(uint32_t*)&w1;
    }
}

// ============================================================================
// LayerNorm over 512 — writes fp16 g_xnh
// ============================================================================
__global__ void k_layernorm(const float* __restrict__ s, const float* __restrict__ b) {
    __shared__ float ssum[4], ssq[4];
    int tid = threadIdx.x;
    int row = blockIdx.x;
    float4 v = ((const float4*)(g_x + (size_t)row * 512))[tid];
    float sum = v.x + v.y + v.z + v.w;
    float sq  = v.x * v.x + v.y * v.y + v.z * v.z + v.w * v.w;
#pragma unroll
    for (int o = 16; o; o >>= 1) {
        sum += __shfl_xor_sync(0xffffffffu, sum, o);
        sq  += __shfl_xor_sync(0xffffffffu, sq, o);
    }
    if ((tid & 31) == 0) { ssum[tid >> 5] = sum; ssq[tid >> 5] = sq; }
    __syncthreads();
    float ts = ssum[0] + ssum[1] + ssum[2] + ssum[3];
    float tq = ssq[0] + ssq[1] + ssq[2] + ssq[3];
    float mean = ts * (1.0f / 512.0f);
    float var  = tq * (1.0f / 512.0f) - mean * mean;
    float rstd = rsqrtf(var + 1e-5f);
    int d = tid << 2;
    float4 sv = *(const float4*)(s + d);
    float4 bv = *(const float4*)(b + d);
    __half2 h0 = __floats2half2_rn((v.x - mean) * rstd * sv.x + bv.x,
                                   (v.y - mean) * rstd * sv.y + bv.y);
    __half2 h1 = __floats2half2_rn((v.z - mean) * rstd * sv.z + bv.z,
                                   (v.w - mean) * rstd * sv.w + bv.w);
    uint2 u; u.x = *(uint32_t*)&h0; u.y = *(uint32_t*)&h1;
    *(uint2*)(g_xnh + (size_t)row * 512 + d) = u;
}

// ============================================================================
// final layout: out[b][d][n] = g_x[b][n][d]
// ============================================================================
__global__ void k_out(float* __restrict__ out) {
    __shared__ float t[32][33];
    int bb = blockIdx.z;
    int n0 = blockIdx.x * 32, d0 = blockIdx.y * 32;
    int tx = threadIdx.x, ty = threadIdx.y;
#pragma unroll
    for (int i = 0; i < 32; i += 8)
        t[ty + i][tx] = g_x[((size_t)bb * 1024 + n0 + ty + i) * 512 + d0 + tx];
    __syncthreads();
#pragma unroll
    for (int i = 0; i < 32; i += 8)
        out[((size_t)bb * 512 + d0 + ty + i) * 1024 + n0 + tx] = t[tx][ty + i];
}

// ============================================================================
// host orchestration
// ============================================================================
extern "C" void kernel_launch(void* const* d_in, const int* in_sizes, int n_in,
                              void* d_out, int out_size) {
    const float *img = 0, *patch_w = 0, *patch_b = 0, *pos_emb = 0;
    const float *ln1_s = 0, *ln1_b = 0, *ln2_s = 0, *ln2_b = 0;
    const float *qkv_w[3] = {0, 0, 0}, *out_w[3] = {0, 0, 0}, *out_b[3] = {0, 0, 0};
    const float *tbl[3] = {0, 0, 0};
    const float *ff_w1 = 0, *ff_b1 = 0, *ff_w2 = 0, *ff_b2 = 0;
    int c512 = 0, c1536 = 0, c393 = 0;
    for (int i = 0; i < n_in; i++) {
        const float* p = (const float*)d_in[i];
        switch (in_sizes[i]) {
            case 134217728: img = p; break;
            case 16777216: patch_w = p; break;
            case 524288:   pos_emb = p; break;
            case 512: {
                const float** t[4] = {&patch_b, &out_b[0], &out_b[1], &out_b[2]};
                if (c512 < 4) *t[c512] = p;
                c512++;
            } break;
            case 1536: {
                const float** t[5] = {&ln1_s, &ln1_b, &ln2_s, &ln2_b, &ff_b2};
                if (c1536 < 5) *t[c1536] = p;
                c1536++;
            } break;
            case 768:    ff_b1 = p; break;
            case 196608: qkv_w[0] = p; break;
            case 393216: {
                const float** t[3] = {&qkv_w[1], &ff_w1, &ff_w2};
                if (c393 < 3) *t[c393] = p;
                c393++;
            } break;
            case 786432: qkv_w[2] = p; break;
            case 65536:  out_w[0] = p; break;
            case 131072: out_w[1] = p; break;
            case 262144: out_w[2] = p; break;
            case 7938:   tbl[0] = p; break;
            case 15876:  tbl[1] = p; break;
            case 31752:  tbl[2] = p; break;
            default: break;
        }
    }

    bool ok = img && patch_w && patch_b && pos_emb && ln1_s && ln1_b && ln2_s &&
              ln2_b && ff_w1 && ff_b1 && ff_w2 && ff_b2;
    for (int l = 0; l < 3; l++)
        ok = ok && qkv_w[l] && out_w[l] && out_b[l] && tbl[l];
    if (!ok) {
        k_zero<<<(out_size + 255) / 256, 256>>>((float*)d_out, out_size);
        return;
    }

    const int PATCH_SMEM = 32768 + 16384;                    // 49152 B
    const int ATT_SMEM   = 16384 + 16384 + 36864 + 65536;    // 135168 B
    cudaFuncSetAttribute(k_patch_h,
                         cudaFuncAttributeMaxDynamicSharedMemorySize, PATCH_SMEM);
    cudaFuncSetAttribute(k_attn_fused,
                         cudaFuncAttributeMaxDynamicSharedMemorySize, ATT_SMEM);

    k_permute_pw<<<(4096 * 512 + 255) / 256, 256>>>(patch_w);
    k_patch_h<<<dim3(4, 16, 2), 256, PATCH_SMEM>>>(img);
    k_patch_sum<<<(4096 * 128 + 255) / 256, 256>>>(patch_b, pos_emb);

    // weight offsets in g_wtsh (halves)
    const u64 QKV_OFF[3] = {0ULL, 196608ULL, 589824ULL};
    const u64 OUT_OFF[3] = {1376256ULL, 1441792ULL, 1572864ULL};
    const u64 FF1_OFF = 1835008ULL;
    const u64 FF2_OFF = 2228224ULL;
    const int heads[3] = {2, 4, 8};
    for (int l = 0; l < 3; l++) {
        int inner = 64 * heads[l];
        int qkvld = 3 * inner;
        int nq = (512 / 8) * qkvld;
        k_cvt_t<<<(nq + 255) / 256, 256>>>(qkv_w[l], QKV_OFF[l], 512, qkvld);
        int no = (inner / 8) * 512;
        k_cvt_t<<<(no + 255) / 256, 256>>>(out_w[l], OUT_OFF[l], inner, 512);
        k_cvt_t<<<(64 * 256 + 255) / 256, 256>>>(ff_w1 + (size_t)l * 512 * 256,
                                                 FF1_OFF + (u64)l * 131072, 512, 256);
        k_cvt_t<<<(32 * 512 + 255) / 256, 256>>>(ff_w2 + (size_t)l * 256 * 512,
                                                 FF2_OFF + (u64)l * 131072, 256, 512);
    }

    for (int l = 0; l < 3; l++) {
        int h = heads[l];
        int inner = 64 * h;
        int qkvld = 3 * inner;

        // ---- attention ----
        k_layernorm<<<4096, 128>>>(ln1_s + l * 512, ln1_b + l * 512);
        k_gemm_h<<<dim3(qkvld / 128, 32), 512>>>(
            HBUF_XN, 512, QKV_OFF[l], HBUF_QKV, qkvld, nullptr, 0, 0);
        k_attn_fused<<<dim3(8, 4 * h), 256, ATT_SMEM>>>(tbl[l], qkvld, inner, h);
        k_gemm_h<<<dim3(4, 32), 512>>>(
            HBUF_O, inner, OUT_OFF[l], -1, 512, out_b[l], 1, 0);

        // ---- feed-forward ----
        k_layernorm<<<4096, 128>>>(ln2_s + l * 512, ln2_b + l * 512);
        k_gemm_h<<<dim3(2, 32), 512>>>(
            HBUF_XN, 512, FF1_OFF + (u64)l * 131072, HBUF_H, 256,
            ff_b1 + l * 256, 0, 1);
        k_gemm_h<<<dim3(4, 32), 512>>>(
            HBUF_H, 256, FF2_OFF + (u64)l * 131072, -1, 512,
            ff_b2 + l * 512, 1, 0);
    }

    k_out<<<dim3(32, 16, 4), dim3(32, 8)>>>((float*)d_out);
}

// round 14
// speedup vs baseline: 1.3656x; 1.3656x over previous
#include <cuda_runtime.h>
#include <cuda_fp16.h>
#include <math.h>
#include <stdint.h>

typedef unsigned long long u64;

// ---------------- problem constants ----------------
// B=4, C=128, H=W=512, P=16, GH=GW=32, N=1024, PATCH_DIM=32768, DIM=512,
// MLP=256, DH=64, HEADS=(2,4,8), NUM_REL=3969

// ---------------- scratch (device globals) ----------------
__device__ __align__(16) __half g_pw2h[32768 * 512]; // patch_w fp16 [d][k']
__device__ __align__(16) float g_x[4096 * 512];      // residual stream (fp32)
__device__ __align__(16) float g_xn[4096 * 512];     // LN output (tf32-rounded)
__device__ __align__(16) float g_qkv[4096 * 1536];   // qkv (tf32-rounded)
__device__ __align__(16) float g_attn[4194304];      // patch split-K partials
__device__ __align__(16) float g_o[4096 * 512];      // attention out (tf32-rounded)
__device__ __align__(16) float g_h[4096 * 256];      // FFN hidden (tf32-rounded)
__device__ __align__(16) float g_wts[2621440];       // tf32-rounded weights

#define BUF_X   0
#define BUF_XN  1
#define BUF_QKV 2
#define BUF_O   3
#define BUF_H   4
__device__ __forceinline__ float* buf(int id) {
    switch (id) {
        case BUF_X:   return g_x;
        case BUF_XN:  return g_xn;
        case BUF_QKV: return g_qkv;
        case BUF_O:   return g_o;
        default:      return g_h;
    }
}

// ============================================================================
__global__ void k_zero(float* o, int n) {
    int i = blockIdx.x * blockDim.x + threadIdx.x;
    if (i < n) o[i] = 0.0f;
}

// ============================================================================
// helpers
// ============================================================================
__device__ __forceinline__ uint32_t f2tf(float f) {
    uint32_t r;
    asm("cvt.rna.tf32.f32 %0, %1;" : "=r"(r) : "f"(f));
    return r;
}
__device__ __forceinline__ float4 cvt4(float4 v) {
    v.x = __uint_as_float(f2tf(v.x));
    v.y = __uint_as_float(f2tf(v.y));
    v.z = __uint_as_float(f2tf(v.z));
    v.w = __uint_as_float(f2tf(v.w));
    return v;
}
__device__ __forceinline__ void mma8(float* c, const uint32_t* a,
                                     uint32_t b0, uint32_t b1) {
    asm("mma.sync.aligned.m16n8k8.row.col.f32.tf32.tf32.f32 "
        "{%0,%1,%2,%3},{%4,%5,%6,%7},{%8,%9},{%0,%1,%2,%3};"
        : "+f"(c[0]), "+f"(c[1]), "+f"(c[2]), "+f"(c[3])
        : "r"(a[0]), "r"(a[1]), "r"(a[2]), "r"(a[3]), "r"(b0), "r"(b1));
}
__device__ __forceinline__ void mma16(float* c, const uint32_t* a,
                                      uint32_t b0, uint32_t b1) {
    asm("mma.sync.aligned.m16n8k16.row.col.f32.f16.f16.f32 "
        "{%0,%1,%2,%3},{%4,%5,%6,%7},{%8,%9},{%0,%1,%2,%3};"
        : "+f"(c[0]), "+f"(c[1]), "+f"(c[2]), "+f"(c[3])
        : "r"(a[0]), "r"(a[1]), "r"(a[2]), "r"(a[3]), "r"(b0), "r"(b1));
}
__device__ __forceinline__ uint32_t ldu(const float* p) {
    return __float_as_uint(*p);
}
__device__ __forceinline__ uint32_t smem_u32(const void* p) {
    return (uint32_t)__cvta_generic_to_shared(p);
}
__device__ __forceinline__ void cpa16(uint32_t s, const void* g) {
    asm volatile("cp.async.cg.shared.global [%0], [%1], 16;" :: "r"(s), "l"(g));
}
__device__ __forceinline__ void cpcommit() {
    asm volatile("cp.async.commit_group;");
}
__device__ __forceinline__ void cpwait0() {
    asm volatile("cp.async.wait_group 0;" ::: "memory");
}

// ============================================================================
// permute patch_w to fp16 [d][k']
// ============================================================================
__global__ void k_permute_pw(const float* __restrict__ pw) {
    int idx = blockIdx.x * blockDim.x + threadIdx.x;   // 4096 * 512
    if (idx >= 4096 * 512) return;
    int k8 = idx >> 9;
    int d  = idx & 511;
    int kp = k8 * 8;
    int c  = kp >> 8;
    int p  = kp & 255;
    __half2 h[4];
#pragma unroll
    for (int i = 0; i < 4; i++) {
        float v0 = pw[(size_t)((p + 2 * i) * 128 + c) * 512 + d];
        float v1 = pw[(size_t)((p + 2 * i + 1) * 128 + c) * 512 + d];
        h[i] = __floats2half2_rn(v0, v1);
    }
    uint4 u;
    u.x = *(uint32_t*)&h[0]; u.y = *(uint32_t*)&h[1];
    u.z = *(uint32_t*)&h[2]; u.w = *(uint32_t*)&h[3];
    *(uint4*)&g_pw2h[(size_t)d * 32768 + kp] = u;
}

// ============================================================================
// batched weight rounding: all 8 weights tf32-rounded in ONE launch
// ============================================================================
struct CvtJobs {
    const float* src[8];
    u64 dst[8];
    int cum[9];     // cumulative float4 counts
};
__global__ void k_cvt_all(CvtJobs jobs) {
    int i = blockIdx.x * blockDim.x + threadIdx.x;
    if (i >= jobs.cum[8]) return;
    int s = 0;
#pragma unroll
    for (int t = 1; t < 8; t++) s += (i >= jobs.cum[t]);
    int loc = i - jobs.cum[s];
    ((float4*)(g_wts + jobs.dst[s]))[loc] =
        cvt4(((const float4*)jobs.src[s])[loc]);
}

// ============================================================================
// patch embed GEMM, split-K partials — fp16 m16n8k16, fp32 accum. (R12)
// ============================================================================
__global__ __launch_bounds__(256, 1)
void k_patch_h(const float* __restrict__ img) {
    extern __shared__ char smc[];
    char* Ab0 = smc;                 // 2 x 256*64 = 32768 B
    char* Bb0 = smc + 32768;         // 2 x 128*64 = 16384 B

    const int tid  = threadIdx.x;
    const int lane = tid & 31;
    const int wid  = tid >> 5;
    const int warp_m = (wid & 3) * 64;
    const int warp_n = (wid >> 2) * 64;
    const int m0 = blockIdx.y * 256;
    const int n0 = blockIdx.x * 128;
    const int kHalf = blockIdx.z;
    const int kBase = kHalf * 16384;

    const int kg = tid & 3;
    const int am = tid >> 2;
    const float* abase[4];
#pragma unroll
    for (int t = 0; t < 4; t++) {
        int m_g = m0 + am + t * 64;
        int bb  = m_g >> 10;
        int tok = m_g & 1023;
        int gh = tok >> 5, gw = tok & 31;
        abase[t] = img + (size_t)bb * 33554432 + (size_t)(gh * 16) * 512 + gw * 16;
    }
    const int bn = tid >> 2;
    const __half* bbase[2];
#pragma unroll
    for (int t = 0; t < 2; t++)
        bbase[t] = g_pw2h + (size_t)(n0 + bn + t * 64) * 32768 + kg * 8;

    const int aSw = (kg ^ ((am >> 1) & 3)) << 4;
    const int bSw = (kg ^ ((bn >> 1) & 3)) << 4;
    int aSt[4], bSt[2];
#pragma unroll
    for (int t = 0; t < 4; t++) aSt[t] = (am + 64 * t) * 64 + aSw;
#pragma unroll
    for (int t = 0; t < 2; t++) bSt[t] = (bn + 64 * t) * 64 + bSw;

    const int kb4 = (lane & 3) * 4;

    float c[4][8][4];
#pragma unroll
    for (int i = 0; i < 4; i++)
#pragma unroll
        for (int j = 0; j < 8; j++)
#pragma unroll
            for (int q = 0; q < 4; q++) c[i][j][q] = 0.0f;

    float4 pa[4][2];

    {
        int k = kBase + kg * 8;
        int cc = k >> 8, rem = k & 255;
        const size_t aoff = (size_t)cc * 262144 + (rem >> 4) * 512 + (rem & 15);
#pragma unroll
        for (int t = 0; t < 4; t++) {
            pa[t][0] = *(const float4*)(abase[t] + aoff);
            pa[t][1] = *(const float4*)(abase[t] + aoff + 4);
        }
#pragma unroll
        for (int t = 0; t < 2; t++)
            cpa16(smem_u32(Bb0 + bSt[t]), bbase[t] + kBase);
        cpcommit();
#pragma unroll
        for (int t = 0; t < 4; t++) {
            __half2 h0 = __floats2half2_rn(pa[t][0].x, pa[t][0].y);
            __half2 h1 = __floats2half2_rn(pa[t][0].z, pa[t][0].w);
            __half2 h2 = __floats2half2_rn(pa[t][1].x, pa[t][1].y);
            __half2 h3 = __floats2half2_rn(pa[t][1].z, pa[t][1].w);
            uint4 u;
            u.x = *(uint32_t*)&h0; u.y = *(uint32_t*)&h1;
            u.z = *(uint32_t*)&h2; u.w = *(uint32_t*)&h3;
            *(uint4*)(Ab0 + aSt[t]) = u;
        }
    }

    for (int it = 0; it < 512; it++) {
        if (it < 511) {
            int k = kBase + (it + 1) * 32 + kg * 8;
            int cc = k >> 8, rem = k & 255;
            const size_t aoff = (size_t)cc * 262144 + (rem >> 4) * 512 + (rem & 15);
#pragma unroll
            for (int t = 0; t < 4; t++) {
                pa[t][0] = *(const float4*)(abase[t] + aoff);
                pa[t][1] = *(const float4*)(abase[t] + aoff + 4);
            }
        }
        cpwait0();
        __syncthreads();
        const int bsel = it & 1;
        const int nsel = bsel ^ 1;
        if (it < 511) {
            int kNext = kBase + (it + 1) * 32;
#pragma unroll
            for (int t = 0; t < 2; t++)
                cpa16(smem_u32(Bb0 + nsel * 8192 + bSt[t]), bbase[t] + kNext);
            cpcommit();
        }

        const char* Asb = Ab0 + bsel * 16384;
        const char* Bsb = Bb0 + bsel * 8192;
#pragma unroll
        for (int s = 0; s < 2; s++) {
            const int gl0 = s * 2, gl1 = s * 2 + 1;
            uint32_t af[4][4];
#pragma unroll
            for (int ma = 0; ma < 4; ma++) {
                int r0 = warp_m + ma * 16 + (lane >> 2);
                int r1 = r0 + 8;
                int x0 = (r0 >> 1) & 3, x1 = (r1 >> 1) & 3;
                af[ma][0] = *(const uint32_t*)(Asb + r0 * 64 + ((gl0 ^ x0) << 4) + kb4);
                af[ma][1] = *(const uint32_t*)(Asb + r1 * 64 + ((gl0 ^ x1) << 4) + kb4);
                af[ma][2] = *(const uint32_t*)(Asb + r0 * 64 + ((gl1 ^ x0) << 4) + kb4);
                af[ma][3] = *(const uint32_t*)(Asb + r1 * 64 + ((gl1 ^ x1) << 4) + kb4);
            }
#pragma unroll
            for (int na = 0; na < 8; na++) {
                int n = warp_n + na * 8 + (lane >> 2);
                int xn = (n >> 1) & 3;
                uint32_t b0 = *(const uint32_t*)(Bsb + n * 64 + ((gl0 ^ xn) << 4) + kb4);
                uint32_t b1 = *(const uint32_t*)(Bsb + n * 64 + ((gl1 ^ xn) << 4) + kb4);
#pragma unroll
                for (int ma = 0; ma < 4; ma++)
                    mma16(c[ma][na], af[ma], b0, b1);
            }
        }

        if (it < 511) {
#pragma unroll
            for (int t = 0; t < 4; t++) {
                __half2 h0 = __floats2half2_rn(pa[t][0].x, pa[t][0].y);
                __half2 h1 = __floats2half2_rn(pa[t][0].z, pa[t][0].w);
                __half2 h2 = __floats2half2_rn(pa[t][1].x, pa[t][1].y);
                __half2 h3 = __floats2half2_rn(pa[t][1].z, pa[t][1].w);
                uint4 u;
                u.x = *(uint32_t*)&h0; u.y = *(uint32_t*)&h1;
                u.z = *(uint32_t*)&h2; u.w = *(uint32_t*)&h3;
                *(uint4*)(Ab0 + nsel * 16384 + aSt[t]) = u;
            }
        }
    }

    float* part = g_attn + (size_t)kHalf * 2097152;
#pragma unroll
    for (int ma = 0; ma < 4; ma++) {
        int r0 = m0 + warp_m + ma * 16 + (lane >> 2);
        int r1 = r0 + 8;
#pragma unroll
        for (int na = 0; na < 8; na++) {
            int col = n0 + warp_n + na * 8 + (lane & 3) * 2;
            *(float2*)(part + (size_t)r0 * 512 + col) = make_float2(c[ma][na][0], c[ma][na][1]);
            *(float2*)(part + (size_t)r1 * 512 + col) = make_float2(c[ma][na][2], c[ma][na][3]);
        }
    }
}

// ============================================================================
// combine split-K partials:  g_x = p0 + p1 + patch_b + pos_emb  (fp32)
// ============================================================================
__global__ void k_patch_sum(const float* __restrict__ pb,
                            const float* __restrict__ pos) {
    int idx = blockIdx.x * blockDim.x + threadIdx.x;
    if (idx >= 4096 * 128) return;
    int row = idx >> 7;
    int c4  = idx & 127;
    int tok = row & 1023;
    float4 a = ((const float4*)g_attn)[idx];
    float4 b = ((const float4*)(g_attn + 2097152))[idx];
    float4 pb4 = ((const float4*)pb)[c4];
    float4 ps  = ((const float4*)pos)[(size_t)tok * 128 + c4];
    float4 o;
    o.x = a.x + b.x + pb4.x + ps.x;
    o.y = a.y + b.y + pb4.y + ps.y;
    o.z = a.z + b.z + pb4.z + ps.z;
    o.w = a.w + b.w + pb4.w + ps.w;
    ((float4*)g_x)[idx] = o;
}

// ============================================================================
// layer TC GEMM (tf32, cp.async) — R11/R12 validated
// ============================================================================
template<int BN>
__global__ __launch_bounds__(BN * 4, 1)
void k_tc_nn(int aId, int ldA, u64 bOff, int ldB,
             int cId, int ldC, int K,
             const float* __restrict__ bias, int addResid, int gelu, int rnd) {
    constexpr int NT = BN * 4;
    constexpr int AROWS = NT / 8;
    constexpr int BCH = BN / 4;
    constexpr int BPAD = BN + 8;

    __shared__ __align__(16) float As[2][128 * 32];
    __shared__ __align__(16) float Bs[2][32 * BPAD];

    const int tid  = threadIdx.x;
    const int lane = tid & 31;
    const int wid  = tid >> 5;
    const int warp_m = (wid & 3) * 32;
    const int warp_n = (wid >> 2) * 32;
    const int m0 = blockIdx.y * 128;
    const int n0 = blockIdx.x * BN;

    const float* A = buf(aId);
    const float* Bw = g_wts + bOff;
    float* C = buf(cId);

    const int aq = tid & 7;
    const int am = tid >> 3;
    const int bc = tid % BCH;
    const int bk = tid / BCH;

    const int aw = am * 32 + ((aq ^ (am & 7)) << 2);
    const int bw = bk * BPAD + bc * 4;

    float c[2][4][4];
#pragma unroll
    for (int i = 0; i < 2; i++)
#pragma unroll
        for (int j = 0; j < 4; j++)
#pragma unroll
            for (int q = 0; q < 4; q++) c[i][j][q] = 0.0f;

    {
#pragma unroll
        for (int t = 0; t < 2; t++)
            cpa16(smem_u32(&As[0][aw + t * AROWS * 32]),
                  A + (size_t)(m0 + am + t * AROWS) * ldA + aq * 4);
#pragma unroll
        for (int t = 0; t < 2; t++)
            cpa16(smem_u32(&Bs[0][bw + t * 16 * BPAD]),
                  Bw + (size_t)(bk + t * 16) * ldB + n0 + bc * 4);
        cpcommit();
    }

    const int iters = K >> 5;
    for (int it = 0; it < iters; it++) {
        cpwait0();
        __syncthreads();
        const int bsel = it & 1;
        const int nsel = bsel ^ 1;
        if (it < iters - 1) {
            int k0 = (it + 1) * 32;
#pragma unroll
            for (int t = 0; t < 2; t++)
                cpa16(smem_u32(&As[nsel][aw + t * AROWS * 32]),
                      A + (size_t)(m0 + am + t * AROWS) * ldA + k0 + aq * 4);
#pragma unroll
            for (int t = 0; t < 2; t++)
                cpa16(smem_u32(&Bs[nsel][bw + t * 16 * BPAD]),
                      Bw + (size_t)(k0 + bk + t * 16) * ldB + n0 + bc * 4);
            cpcommit();
        }

        const float* Asb = As[bsel];
        const float* Bsb = Bs[bsel];
#pragma unroll
        for (int kk = 0; kk < 4; kk++) {
            uint32_t af[2][4], bf[4][2];
            const int kq0 = kk * 2, kq1 = kk * 2 + 1;
            const int kb  = lane & 3;
#pragma unroll
            for (int ma = 0; ma < 2; ma++) {
                int r0 = warp_m + ma * 16 + (lane >> 2);
                int r1 = r0 + 8;
                af[ma][0] = ldu(&Asb[r0 * 32 + ((kq0 ^ (r0 & 7)) << 2) + kb]);
                af[ma][1] = ldu(&Asb[r1 * 32 + ((kq0 ^ (r1 & 7)) << 2) + kb]);
                af[ma][2] = ldu(&Asb[r0 * 32 + ((kq1 ^ (r0 & 7)) << 2) + kb]);
                af[ma][3] = ldu(&Asb[r1 * 32 + ((kq1 ^ (r1 & 7)) << 2) + kb]);
            }
#pragma unroll
            for (int na = 0; na < 4; na++) {
                int n = warp_n + na * 8 + (lane >> 2);
                bf[na][0] = ldu(&Bsb[(kk * 8 + kb) * BPAD + n]);
                bf[na][1] = ldu(&Bsb[(kk * 8 + 4 + kb) * BPAD + n]);
            }
#pragma unroll
            for (int ma = 0; ma < 2; ma++)
#pragma unroll
                for (int na = 0; na < 4; na++)
                    mma8(c[ma][na], af[ma], bf[na][0], bf[na][1]);
        }
    }

#pragma unroll
    for (int ma = 0; ma < 2; ma++) {
        int r0 = m0 + warp_m + ma * 16 + (lane >> 2);
        int r1 = r0 + 8;
#pragma unroll
        for (int na = 0; na < 4; na++) {
            int col = n0 + warp_n + na * 8 + (lane & 3) * 2;
            float v[4] = {c[ma][na][0], c[ma][na][1], c[ma][na][2], c[ma][na][3]};
            if (bias) {
                float b0 = bias[col], b1 = bias[col + 1];
                v[0] += b0; v[1] += b1; v[2] += b0; v[3] += b1;
            }
            if (gelu) {
#pragma unroll
                for (int q = 0; q < 4; q++)
                    v[q] = 0.5f * v[q] * (1.0f + erff(v[q] * 0.70710678118654752f));
            }
            if (addResid) {
                v[0] += g_x[(size_t)r0 * 512 + col];
                v[1] += g_x[(size_t)r0 * 512 + col + 1];
                v[2] += g_x[(size_t)r1 * 512 + col];
                v[3] += g_x[(size_t)r1 * 512 + col + 1];
            }
            if (rnd) {
#pragma unroll
                for (int q = 0; q < 4; q++)
                    v[q] = __uint_as_float(f2tf(v[q]));
            }
            *(float2*)(C + (size_t)r0 * ldC + col) = make_float2(v[0], v[1]);
            *(float2*)(C + (size_t)r1 * ldC + col) = make_float2(v[2], v[3]);
        }
    }
}

// ============================================================================
// FUSED attention (FlashAttention-2 style, tf32) — R11/R12 validated
// ============================================================================
__global__ __launch_bounds__(256, 1)
void k_attn_fused(const float* __restrict__ tbl, int qkvld, int inner, int hc) {
    extern __shared__ float sm[];
    float* Qs = sm;
    float* Ks = sm + 8192;
    float* Vs = sm + 8192 + 8704;
    float* Ps = sm + 8192 + 8704 + 9216;

    const int tid  = threadIdx.x;
    const int lane = tid & 31;
    const int wid  = tid >> 5;
    const int i0 = blockIdx.x * 128;
    const int z  = blockIdx.y;
    const int bb = z / hc, head = z % hc;
    const float* Qb = g_qkv + (size_t)bb * 1024 * qkvld + head * 64;
    const float* Kb = Qb + inner;
    const float* Vb = Qb + 2 * inner;

    {
        const int aq = tid & 15;
        const int am = tid >> 4;
#pragma unroll
        for (int t = 0; t < 8; t++) {
            int m = am + t * 16;
            float4 v = *(const float4*)(Qb + (size_t)(i0 + m) * qkvld + aq * 4);
            int p = (aq & 8) | ((aq ^ (m & 7)) & 7);
            *(float4*)&Qs[m * 64 + (p << 2)] = v;
        }
    }

    const int rl0 = wid * 16 + (lane >> 2);
    const int rl1 = rl0 + 8;
    const int gr0 = i0 + rl0, gr1 = i0 + rl1;
    const int ih0 = gr0 >> 5, iw0 = gr0 & 31;
    const int ih1 = gr1 >> 5, iw1 = gr1 & 31;
    const int kb  = lane & 3;

    float o[8][4];
#pragma unroll
    for (int j = 0; j < 8; j++) { o[j][0] = o[j][1] = o[j][2] = o[j][3] = 0.f; }
    float m0 = -1e30f, m1 = -1e30f, l0 = 0.f, l1 = 0.f;

    for (int jt = 0; jt < 8; jt++) {
        const int j0 = jt * 128;
        __syncthreads();
        {
            const int n = tid & 127;
            const int cc = tid >> 7;
#pragma unroll
            for (int t = 0; t < 8; t++) {
                int kq = cc + t * 2;
                float4 v = *(const float4*)(Kb + (size_t)(j0 + n) * qkvld + kq * 4);
                Ks[(kq * 4 + 0) * 136 + n] = v.x;
                Ks[(kq * 4 + 1) * 136 + n] = v.y;
                Ks[(kq * 4 + 2) * 136 + n] = v.z;
                Ks[(kq * 4 + 3) * 136 + n] = v.w;
            }
        }
        {
#pragma unroll
            for (int t = 0; t < 8; t++) {
                int idx = tid + t * 256;
                int row = idx >> 4, c4 = idx & 15;
                float4 v = *(const float4*)(Vb + (size_t)(j0 + row) * qkvld + c4 * 4);
                *(float4*)&Vs[row * 72 + c4 * 4] = v;
            }
        }
        __syncthreads();

        float s[16][4];
#pragma unroll
        for (int na = 0; na < 16; na++) { s[na][0] = s[na][1] = s[na][2] = s[na][3] = 0.f; }
#pragma unroll
        for (int kk = 0; kk < 8; kk++) {
            uint32_t af[4];
            int kq0 = kk * 2, kq1 = kk * 2 + 1;
            int p00 = (kq0 & 8) | ((kq0 ^ (rl0 & 7)) & 7);
            int p01 = (kq0 & 8) | ((kq0 ^ (rl1 & 7)) & 7);
            int p10 = (kq1 & 8) | ((kq1 ^ (rl0 & 7)) & 7);
            int p11 = (kq1 & 8) | ((kq1 ^ (rl1 & 7)) & 7);
            af[0] = ldu(&Qs[rl0 * 64 + (p00 << 2) + kb]);
            af[1] = ldu(&Qs[rl1 * 64 + (p01 << 2) + kb]);
            af[2] = ldu(&Qs[rl0 * 64 + (p10 << 2) + kb]);
            af[3] = ldu(&Qs[rl1 * 64 + (p11 << 2) + kb]);
#pragma unroll
            for (int na = 0; na < 16; na++) {
                int n = na * 8 + (lane >> 2);
                uint32_t b0 = ldu(&Ks[(kk * 8 + kb) * 136 + n]);
                uint32_t b1 = ldu(&Ks[(kk * 8 + 4 + kb) * 136 + n]);
                mma8(s[na], af, b0, b1);
            }
        }
#pragma unroll
        for (int na = 0; na < 16; na++) {
            int jj = j0 + na * 8 + (lane & 3) * 2;
            int jh0 = jj >> 5, jw0 = jj & 31;
            int jh1 = (jj + 1) >> 5, jw1 = (jj + 1) & 31;
            s[na][0] = s[na][0] * 0.125f + tbl[(size_t)((ih0 - jh0 + 31) * 63 + (iw0 - jw0 + 31)) * hc + head];
            s[na][1] = s[na][1] * 0.125f + tbl[(size_t)((ih0 - jh1 + 31) * 63 + (iw0 - jw1 + 31)) * hc + head];
            s[na][2] = s[na][2] * 0.125f + tbl[(size_t)((ih1 - jh0 + 31) * 63 + (iw1 - jw0 + 31)) * hc + head];
            s[na][3] = s[na][3] * 0.125f + tbl[(size_t)((ih1 - jh1 + 31) * 63 + (iw1 - jw1 + 31)) * hc + head];
        }
        float mx0 = -1e30f, mx1 = -1e30f;
#pragma unroll
        for (int na = 0; na < 16; na++) {
            mx0 = fmaxf(mx0, fmaxf(s[na][0], s[na][1]));
            mx1 = fmaxf(mx1, fmaxf(s[na][2], s[na][3]));
        }
        mx0 = fmaxf(mx0, __shfl_xor_sync(0xffffffffu, mx0, 1));
        mx0 = fmaxf(mx0, __shfl_xor_sync(0xffffffffu, mx0, 2));
        mx1 = fmaxf(mx1, __shfl_xor_sync(0xffffffffu, mx1, 1));
        mx1 = fmaxf(mx1, __shfl_xor_sync(0xffffffffu, mx1, 2));
        float mn0 = fmaxf(m0, mx0), mn1 = fmaxf(m1, mx1);
        float al0 = __expf(m0 - mn0), al1 = __expf(m1 - mn1);
        float ls0 = 0.f, ls1 = 0.f;
#pragma unroll
        for (int na = 0; na < 16; na++) {
            s[na][0] = __expf(s[na][0] - mn0);
            s[na][1] = __expf(s[na][1] - mn0);
            s[na][2] = __expf(s[na][2] - mn1);
            s[na][3] = __expf(s[na][3] - mn1);
            ls0 += s[na][0] + s[na][1];
            ls1 += s[na][2] + s[na][3];
        }
        ls0 += __shfl_xor_sync(0xffffffffu, ls0, 1);
        ls0 += __shfl_xor_sync(0xffffffffu, ls0, 2);
        ls1 += __shfl_xor_sync(0xffffffffu, ls1, 1);
        ls1 += __shfl_xor_sync(0xffffffffu, ls1, 2);
        l0 = l0 * al0 + ls0;
        l1 = l1 * al1 + ls1;
        m0 = mn0; m1 = mn1;
#pragma unroll
        for (int j = 0; j < 8; j++) {
            o[j][0] *= al0; o[j][1] *= al0; o[j][2] *= al1; o[j][3] *= al1;
        }
#pragma unroll
        for (int na = 0; na < 16; na++) {
            int c = na * 8 + (lane & 3) * 2;
            int g = c >> 2;
            int a0 = rl0 * 128 + ((g ^ (rl0 & 7)) << 2) + (c & 3);
            int a1 = rl1 * 128 + ((g ^ (rl1 & 7)) << 2) + (c & 3);
            Ps[a0]     = __uint_as_float(f2tf(s[na][0]));
            Ps[a0 + 1] = __uint_as_float(f2tf(s[na][1]));
            Ps[a1]     = __uint_as_float(f2tf(s[na][2]));
            Ps[a1 + 1] = __uint_as_float(f2tf(s[na][3]));
        }
        __syncthreads();
#pragma unroll
        for (int kk = 0; kk < 16; kk++) {
            uint32_t af[4];
            int g0 = kk * 2, g1 = kk * 2 + 1;
            af[0] = ldu(&Ps[rl0 * 128 + ((g0 ^ (rl0 & 7)) << 2) + kb]);
            af[1] = ldu(&Ps[rl1 * 128 + ((g0 ^ (rl1 & 7)) << 2) + kb]);
            af[2] = ldu(&Ps[rl0 * 128 + ((g1 ^ (rl0 & 7)) << 2) + kb]);
            af[3] = ldu(&Ps[rl1 * 128 + ((g1 ^ (rl1 & 7)) << 2) + kb]);
#pragma unroll
            for (int na = 0; na < 8; na++) {
                int n = na * 8 + (lane >> 2);
                uint32_t b0 = ldu(&Vs[(kk * 8 + kb) * 72 + n]);
                uint32_t b1 = ldu(&Vs[(kk * 8 + 4 + kb) * 72 + n]);
                mma8(o[na], af, b0, b1);
            }
        }
    }

    float inv0 = 1.0f / l0, inv1 = 1.0f / l1;
    float* Ob = g_o + ((size_t)bb * 1024) * inner + head * 64;
#pragma unroll
    for (int na = 0; na < 8; na++) {
        int col = na * 8 + (lane & 3) * 2;
        float2 w0 = make_float2(__uint_as_float(f2tf(o[na][0] * inv0)),
                                __uint_as_float(f2tf(o[na][1] * inv0)));
        float2 w1 = make_float2(__uint_as_float(f2tf(o[na][2] * inv1)),
                                __uint_as_float(f2tf(o[na][3] * inv1)));
        *(float2*)(Ob + (size_t)gr0 * inner + col) = w0;
        *(float2*)(Ob + (size_t)gr1 * inner + col) = w1;
    }
}

// ============================================================================
// LayerNorm over 512 — warp-per-row (4 rows / 128-thr block), output tf32
// ============================================================================
__global__ void k_layernorm(const float* __restrict__ s, const float* __restrict__ b) {
    int tid  = threadIdx.x;
    int lane = tid & 31;
    int row  = blockIdx.x * 4 + (tid >> 5);
    const float4* rp = (const float4*)(g_x + (size_t)row * 512);
    float4 v[4];
    float sum = 0.f, sq = 0.f;
#pragma unroll
    for (int q = 0; q < 4; q++) {
        v[q] = rp[lane + 32 * q];
        sum += v[q].x + v[q].y + v[q].z + v[q].w;
        sq  += v[q].x * v[q].x + v[q].y * v[q].y + v[q].z * v[q].z + v[q].w * v[q].w;
    }
#pragma unroll
    for (int o = 16; o; o >>= 1) {
        sum += __shfl_xor_sync(0xffffffffu, sum, o);
        sq  += __shfl_xor_sync(0xffffffffu, sq, o);
    }
    float mean = sum * (1.0f / 512.0f);
    float var  = sq * (1.0f / 512.0f) - mean * mean;
    float rstd = rsqrtf(var + 1e-5f);
    float4* op = (float4*)(g_xn + (size_t)row * 512);
#pragma unroll
    for (int q = 0; q < 4; q++) {
        int c4 = lane + 32 * q;
        float4 sv = ((const float4*)s)[c4];
        float4 bv = ((const float4*)b)[c4];
        float4 o;
        o.x = (v[q].x - mean) * rstd * sv.x + bv.x;
        o.y = (v[q].y - mean) * rstd * sv.y + bv.y;
        o.z = (v[q].z - mean) * rstd * sv.z + bv.z;
        o.w = (v[q].w - mean) * rstd * sv.w + bv.w;
        op[c4] = cvt4(o);
    }
}

// ============================================================================
// final layout: out[b][d][n] = g_x[b][n][d]
// ============================================================================
__global__ void k_out(float* __restrict__ out) {
    __shared__ float t[32][33];
    int bb = blockIdx.z;
    int n0 = blockIdx.x * 32, d0 = blockIdx.y * 32;
    int tx = threadIdx.x, ty = threadIdx.y;
#pragma unroll
    for (int i = 0; i < 32; i += 8)
        t[ty + i][tx] = g_x[((size_t)bb * 1024 + n0 + ty + i) * 512 + d0 + tx];
    __syncthreads();
#pragma unroll
    for (int i = 0; i < 32; i += 8)
        out[((size_t)bb * 512 + d0 + ty + i) * 1024 + n0 + tx] = t[tx][ty + i];
}

// ============================================================================
// host orchestration
// ============================================================================
extern "C" void kernel_launch(void* const* d_in, const int* in_sizes, int n_in,
                              void* d_out, int out_size) {
    const float *img = 0, *patch_w = 0, *patch_b = 0, *pos_emb = 0;
    const float *ln1_s = 0, *ln1_b = 0, *ln2_s = 0, *ln2_b = 0;
    const float *qkv_w[3] = {0, 0, 0}, *out_w[3] = {0, 0, 0}, *out_b[3] = {0, 0, 0};
    const float *tbl[3] = {0, 0, 0};
    const float *ff_w1 = 0, *ff_b1 = 0, *ff_w2 = 0, *ff_b2 = 0;
    int c512 = 0, c1536 = 0, c393 = 0;
    for (int i = 0; i < n_in; i++) {
        const float* p = (const float*)d_in[i];
        switch (in_sizes[i]) {
            case 134217728: img = p; break;
            case 16777216: patch_w = p; break;
            case 524288:   pos_emb = p; break;
            case 512: {
                const float** t[4] = {&patch_b, &out_b[0], &out_b[1], &out_b[2]};
                if (c512 < 4) *t[c512] = p;
                c512++;
            } break;
            case 1536: {
                const float** t[5] = {&ln1_s, &ln1_b, &ln2_s, &ln2_b, &ff_b2};
                if (c1536 < 5) *t[c1536] = p;
                c1536++;
            } break;
            case 768:    ff_b1 = p; break;
            case 196608: qkv_w[0] = p; break;
            case 393216: {
                const float** t[3] = {&qkv_w[1], &ff_w1, &ff_w2};
                if (c393 < 3) *t[c393] = p;
                c393++;
            } break;
            case 786432: qkv_w[2] = p; break;
            case 65536:  out_w[0] = p; break;
            case 131072: out_w[1] = p; break;
            case 262144: out_w[2] = p; break;
            case 7938:   tbl[0] = p; break;
            case 15876:  tbl[1] = p; break;
            case 31752:  tbl[2] = p; break;
            default: break;
        }
    }

    bool ok = img && patch_w && patch_b && pos_emb && ln1_s && ln1_b && ln2_s &&
              ln2_b && ff_w1 && ff_b1 && ff_w2 && ff_b2;
    for (int l = 0; l < 3; l++)
        ok = ok && qkv_w[l] && out_w[l] && out_b[l] && tbl[l];
    if (!ok) {
        k_zero<<<(out_size + 255) / 256, 256>>>((float*)d_out, out_size);
        return;
    }

    const int PATCH_SMEM = 32768 + 16384;                    // 49152 B
    const int ATT_SMEM   = (8192 + 8704 + 9216 + 16384) * 4; // 169984 B
    cudaFuncSetAttribute(k_patch_h,
                         cudaFuncAttributeMaxDynamicSharedMemorySize, PATCH_SMEM);
    cudaFuncSetAttribute(k_attn_fused,
                         cudaFuncAttributeMaxDynamicSharedMemorySize, ATT_SMEM);

    k_permute_pw<<<(4096 * 512 + 255) / 256, 256>>>(patch_w);
    k_patch_h<<<dim3(4, 16, 2), 256, PATCH_SMEM>>>(img);
    k_patch_sum<<<(4096 * 128 + 255) / 256, 256>>>(patch_b, pos_emb);

    // weight offsets in g_wts (floats) — single batched rounding launch
    const u64 QKV_OFF[3] = {0ULL, 196608ULL, 589824ULL};
    const u64 OUT_OFF[3] = {1376256ULL, 1441792ULL, 1572864ULL};
    const u64 FF1_OFF = 1835008ULL;
    const u64 FF2_OFF = 2228224ULL;
    {
        CvtJobs j;
        const float* srcs[8] = {qkv_w[0], qkv_w[1], qkv_w[2],
                                out_w[0], out_w[1], out_w[2], ff_w1, ff_w2};
        u64 dsts[8] = {QKV_OFF[0], QKV_OFF[1], QKV_OFF[2],
                       OUT_OFF[0], OUT_OFF[1], OUT_OFF[2], FF1_OFF, FF2_OFF};
        int n4s[8]  = {49152, 98304, 196608, 16384, 32768, 65536, 98304, 98304};
        int cum = 0;
        for (int i = 0; i < 8; i++) {
            j.src[i] = srcs[i]; j.dst[i] = dsts[i]; j.cum[i] = cum; cum += n4s[i];
        }
        j.cum[8] = cum;
        k_cvt_all<<<(cum + 255) / 256, 256>>>(j);
    }

    const int heads[3] = {2, 4, 8};
    for (int l = 0; l < 3; l++) {
        int h = heads[l];
        int inner = 64 * h;
        int qkvld = 3 * inner;

        // ---- attention ----
        k_layernorm<<<1024, 128>>>(ln1_s + l * 512, ln1_b + l * 512);
        k_tc_nn<128><<<dim3(qkvld / 128, 32), 512>>>(
            BUF_XN, 512, QKV_OFF[l], qkvld, BUF_QKV, qkvld, 512,
            nullptr, 0, 0, 1);
        k_attn_fused<<<dim3(8, 4 * h), 256, ATT_SMEM>>>(tbl[l], qkvld, inner, h);
        k_tc_nn<128><<<dim3(4, 32), 512>>>(
            BUF_O, inner, OUT_OFF[l], 512, BUF_X, 512, inner,
            out_b[l], 1, 0, 0);

        // ---- feed-forward ----
        k_layernorm<<<1024, 128>>>(ln2_s + l * 512, ln2_b + l * 512);
        k_tc_nn<128><<<dim3(2, 32), 512>>>(
            BUF_XN, 512, FF1_OFF + (u64)l * 131072, 256, BUF_H, 256, 512,
            ff_b1 + l * 256, 0, 1, 1);
        k_tc_nn<128><<<dim3(4, 32), 512>>>(
            BUF_H, 256, FF2_OFF + (u64)l * 131072, 512, BUF_X, 512, 256,
            ff_b2 + l * 512, 1, 0, 0);
    }

    k_out<<<dim3(32, 16, 4), dim3(32, 8)>>>((float*)d_out);
}

// round 15
// speedup vs baseline: 1.4583x; 1.0679x over previous
#include <cuda_runtime.h>
#include <cuda_fp16.h>
#include <math.h>
#include <stdint.h>

typedef unsigned long long u64;

// ---------------- problem constants ----------------
// B=4, C=128, H=W=512, P=16, GH=GW=32, N=1024, PATCH_DIM=32768, DIM=512,
// MLP=256, DH=64, HEADS=(2,4,8), NUM_REL=3969

// ---------------- scratch (device globals) ----------------
__device__ __align__(16) __half g_pw2h[32768 * 512]; // patch_w fp16 [d][k']
__device__ __align__(16) float  g_x[4096 * 512];     // residual stream (fp32)
__device__ __align__(16) float  g_qkv[4096 * 1536];  // qkv (fp32, tf32-rounded)
__device__ __align__(16) float  g_attn[4194304];     // patch split-K partials
__device__ __align__(16) float  g_o[4096 * 512];     // attention out (tf32-rounded)
__device__ __align__(16) float  g_wts[458752];       // tf32 out_w weights
__device__ __align__(16) __half g_xnh[4096 * 512];   // LN output fp16
__device__ __align__(16) __half g_hh[4096 * 256];    // FFN hidden fp16
__device__ __align__(16) __half g_wtsh[2162688];     // fp16 weights [n][K]

#define BUF_X   0
#define BUF_QKV 1
#define BUF_O   2
__device__ __forceinline__ float* buf(int id) {
    switch (id) {
        case BUF_X:   return g_x;
        case BUF_QKV: return g_qkv;
        default:      return g_o;
    }
}
#define HBUF_XN 0
#define HBUF_H  1
__device__ __forceinline__ __half* bufh(int id) {
    return id == HBUF_XN ? g_xnh : g_hh;
}

// ============================================================================
__global__ void k_zero(float* o, int n) {
    int i = blockIdx.x * blockDim.x + threadIdx.x;
    if (i < n) o[i] = 0.0f;
}

// ============================================================================
// helpers
// ============================================================================
__device__ __forceinline__ uint32_t f2tf(float f) {
    uint32_t r;
    asm("cvt.rna.tf32.f32 %0, %1;" : "=r"(r) : "f"(f));
    return r;
}
__device__ __forceinline__ float4 cvt4(float4 v) {
    v.x = __uint_as_float(f2tf(v.x));
    v.y = __uint_as_float(f2tf(v.y));
    v.z = __uint_as_float(f2tf(v.z));
    v.w = __uint_as_float(f2tf(v.w));
    return v;
}
__device__ __forceinline__ void mma8(float* c, const uint32_t* a,
                                     uint32_t b0, uint32_t b1) {
    asm("mma.sync.aligned.m16n8k8.row.col.f32.tf32.tf32.f32 "
        "{%0,%1,%2,%3},{%4,%5,%6,%7},{%8,%9},{%0,%1,%2,%3};"
        : "+f"(c[0]), "+f"(c[1]), "+f"(c[2]), "+f"(c[3])
        : "r"(a[0]), "r"(a[1]), "r"(a[2]), "r"(a[3]), "r"(b0), "r"(b1));
}
__device__ __forceinline__ void mma16(float* c, const uint32_t* a,
                                      uint32_t b0, uint32_t b1) {
    asm("mma.sync.aligned.m16n8k16.row.col.f32.f16.f16.f32 "
        "{%0,%1,%2,%3},{%4,%5,%6,%7},{%8,%9},{%0,%1,%2,%3};"
        : "+f"(c[0]), "+f"(c[1]), "+f"(c[2]), "+f"(c[3])
        : "r"(a[0]), "r"(a[1]), "r"(a[2]), "r"(a[3]), "r"(b0), "r"(b1));
}
__device__ __forceinline__ uint32_t ldu(const float* p) {
    return __float_as_uint(*p);
}
__device__ __forceinline__ uint32_t smem_u32(const void* p) {
    return (uint32_t)__cvta_generic_to_shared(p);
}
__device__ __forceinline__ void cpa16(uint32_t s, const void* g) {
    asm volatile("cp.async.cg.shared.global [%0], [%1], 16;" :: "r"(s), "l"(g));
}
__device__ __forceinline__ void cpcommit() {
    asm volatile("cp.async.commit_group;");
}
__device__ __forceinline__ void cpwait0() {
    asm volatile("cp.async.wait_group 0;" ::: "memory");
}

// ============================================================================
// permute patch_w to fp16 [d][k']
// ============================================================================
__global__ void k_permute_pw(const float* __restrict__ pw) {
    int idx = blockIdx.x * blockDim.x + threadIdx.x;   // 4096 * 512
    if (idx >= 4096 * 512) return;
    int k8 = idx >> 9;
    int d  = idx & 511;
    int kp = k8 * 8;
    int c  = kp >> 8;
    int p  = kp & 255;
    __half2 h[4];
#pragma unroll
    for (int i = 0; i < 4; i++) {
        float v0 = pw[(size_t)((p + 2 * i) * 128 + c) * 512 + d];
        float v1 = pw[(size_t)((p + 2 * i + 1) * 128 + c) * 512 + d];
        h[i] = __floats2half2_rn(v0, v1);
    }
    uint4 u;
    u.x = *(uint32_t*)&h[0]; u.y = *(uint32_t*)&h[1];
    u.z = *(uint32_t*)&h[2]; u.w = *(uint32_t*)&h[3];
    *(uint4*)&g_pw2h[(size_t)d * 32768 + kp] = u;
}

// ============================================================================
// batched tf32 rounding (out_w only, 3 segments, one launch)
// ============================================================================
struct CvtJobs {
    const float* src[3];
    u64 dst[3];
    int cum[4];
};
__global__ void k_cvt_all(CvtJobs jobs) {
    int i = blockIdx.x * blockDim.x + threadIdx.x;
    if (i >= jobs.cum[3]) return;
    int s = 0;
#pragma unroll
    for (int t = 1; t < 3; t++) s += (i >= jobs.cum[t]);
    int loc = i - jobs.cum[s];
    ((float4*)(g_wts + jobs.dst[s]))[loc] =
        cvt4(((const float4*)jobs.src[s])[loc]);
}

// ============================================================================
// batched fp16 weight transpose [K][N] -> g_wtsh[dst + n*K + k] (9 segments)
// element = one (k8, n): 8 k-values
// ============================================================================
struct TJobs {
    const float* src[9];
    u64 dst[9];
    int K[9];
    int N[9];
    int cum[10];
};
__global__ void k_cvt_t_all(TJobs jobs) {
    int i = blockIdx.x * blockDim.x + threadIdx.x;
    if (i >= jobs.cum[9]) return;
    int s = 0;
#pragma unroll
    for (int t = 1; t < 9; t++) s += (i >= jobs.cum[t]);
    int loc = i - jobs.cum[s];
    int N = jobs.N[s], K = jobs.K[s];
    int n  = loc % N;
    int k  = (loc / N) * 8;
    const float* src = jobs.src[s];
    __half2 h[4];
#pragma unroll
    for (int q = 0; q < 4; q++) {
        float v0 = src[(size_t)(k + 2 * q) * N + n];
        float v1 = src[(size_t)(k + 2 * q + 1) * N + n];
        h[q] = __floats2half2_rn(v0, v1);
    }
    uint4 u;
    u.x = *(uint32_t*)&h[0]; u.y = *(uint32_t*)&h[1];
    u.z = *(uint32_t*)&h[2]; u.w = *(uint32_t*)&h[3];
    *(uint4*)&g_wtsh[jobs.dst[s] + (size_t)n * K + k] = u;
}

// ============================================================================
// patch embed GEMM, split-K partials — fp16 m16n8k16 (R12 validated)
// ============================================================================
__global__ __launch_bounds__(256, 1)
void k_patch_h(const float* __restrict__ img) {
    extern __shared__ char smc[];
    char* Ab0 = smc;
    char* Bb0 = smc + 32768;

    const int tid  = threadIdx.x;
    const int lane = tid & 31;
    const int wid  = tid >> 5;
    const int warp_m = (wid & 3) * 64;
    const int warp_n = (wid >> 2) * 64;
    const int m0 = blockIdx.y * 256;
    const int n0 = blockIdx.x * 128;
    const int kHalf = blockIdx.z;
    const int kBase = kHalf * 16384;

    const int kg = tid & 3;
    const int am = tid >> 2;
    const float* abase[4];
#pragma unroll
    for (int t = 0; t < 4; t++) {
        int m_g = m0 + am + t * 64;
        int bb  = m_g >> 10;
        int tok = m_g & 1023;
        int gh = tok >> 5, gw = tok & 31;
        abase[t] = img + (size_t)bb * 33554432 + (size_t)(gh * 16) * 512 + gw * 16;
    }
    const int bn = tid >> 2;
    const __half* bbase[2];
#pragma unroll
    for (int t = 0; t < 2; t++)
        bbase[t] = g_pw2h + (size_t)(n0 + bn + t * 64) * 32768 + kg * 8;

    const int aSw = (kg ^ ((am >> 1) & 3)) << 4;
    const int bSw = (kg ^ ((bn >> 1) & 3)) << 4;
    int aSt[4], bSt[2];
#pragma unroll
    for (int t = 0; t < 4; t++) aSt[t] = (am + 64 * t) * 64 + aSw;
#pragma unroll
    for (int t = 0; t < 2; t++) bSt[t] = (bn + 64 * t) * 64 + bSw;

    const int kb4 = (lane & 3) * 4;

    float c[4][8][4];
#pragma unroll
    for (int i = 0; i < 4; i++)
#pragma unroll
        for (int j = 0; j < 8; j++)
#pragma unroll
            for (int q = 0; q < 4; q++) c[i][j][q] = 0.0f;

    float4 pa[4][2];

    {
        int k = kBase + kg * 8;
        int cc = k >> 8, rem = k & 255;
        const size_t aoff = (size_t)cc * 262144 + (rem >> 4) * 512 + (rem & 15);
#pragma unroll
        for (int t = 0; t < 4; t++) {
            pa[t][0] = *(const float4*)(abase[t] + aoff);
            pa[t][1] = *(const float4*)(abase[t] + aoff + 4);
        }
#pragma unroll
        for (int t = 0; t < 2; t++)
            cpa16(smem_u32(Bb0 + bSt[t]), bbase[t] + kBase);
        cpcommit();
#pragma unroll
        for (int t = 0; t < 4; t++) {
            __half2 h0 = __floats2half2_rn(pa[t][0].x, pa[t][0].y);
            __half2 h1 = __floats2half2_rn(pa[t][0].z, pa[t][0].w);
            __half2 h2 = __floats2half2_rn(pa[t][1].x, pa[t][1].y);
            __half2 h3 = __floats2half2_rn(pa[t][1].z, pa[t][1].w);
            uint4 u;
            u.x = *(uint32_t*)&h0; u.y = *(uint32_t*)&h1;
            u.z = *(uint32_t*)&h2; u.w = *(uint32_t*)&h3;
            *(uint4*)(Ab0 + aSt[t]) = u;
        }
    }

    for (int it = 0; it < 512; it++) {
        if (it < 511) {
            int k = kBase + (it + 1) * 32 + kg * 8;
            int cc = k >> 8, rem = k & 255;
            const size_t aoff = (size_t)cc * 262144 + (rem >> 4) * 512 + (rem & 15);
#pragma unroll
            for (int t = 0; t < 4; t++) {
                pa[t][0] = *(const float4*)(abase[t] + aoff);
                pa[t][1] = *(const float4*)(abase[t] + aoff + 4);
            }
        }
        cpwait0();
        __syncthreads();
        const int bsel = it & 1;
        const int nsel = bsel ^ 1;
        if (it < 511) {
            int kNext = kBase + (it + 1) * 32;
#pragma unroll
            for (int t = 0; t < 2; t++)
                cpa16(smem_u32(Bb0 + nsel * 8192 + bSt[t]), bbase[t] + kNext);
            cpcommit();
        }

        const char* Asb = Ab0 + bsel * 16384;
        const char* Bsb = Bb0 + bsel * 8192;
#pragma unroll
        for (int s = 0; s < 2; s++) {
            const int gl0 = s * 2, gl1 = s * 2 + 1;
            uint32_t af[4][4];
#pragma unroll
            for (int ma = 0; ma < 4; ma++) {
                int r0 = warp_m + ma * 16 + (lane >> 2);
                int r1 = r0 + 8;
                int x0 = (r0 >> 1) & 3, x1 = (r1 >> 1) & 3;
                af[ma][0] = *(const uint32_t*)(Asb + r0 * 64 + ((gl0 ^ x0) << 4) + kb4);
                af[ma][1] = *(const uint32_t*)(Asb + r1 * 64 + ((gl0 ^ x1) << 4) + kb4);
                af[ma][2] = *(const uint32_t*)(Asb + r0 * 64 + ((gl1 ^ x0) << 4) + kb4);
                af[ma][3] = *(const uint32_t*)(Asb + r1 * 64 + ((gl1 ^ x1) << 4) + kb4);
            }
#pragma unroll
            for (int na = 0; na < 8; na++) {
                int n = warp_n + na * 8 + (lane >> 2);
                int xn = (n >> 1) & 3;
                uint32_t b0 = *(const uint32_t*)(Bsb + n * 64 + ((gl0 ^ xn) << 4) + kb4);
                uint32_t b1 = *(const uint32_t*)(Bsb + n * 64 + ((gl1 ^ xn) << 4) + kb4);
#pragma unroll
                for (int ma = 0; ma < 4; ma++)
                    mma16(c[ma][na], af[ma], b0, b1);
            }
        }

        if (it < 511) {
#pragma unroll
            for (int t = 0; t < 4; t++) {
                __half2 h0 = __floats2half2_rn(pa[t][0].x, pa[t][0].y);
                __half2 h1 = __floats2half2_rn(pa[t][0].z, pa[t][0].w);
                __half2 h2 = __floats2half2_rn(pa[t][1].x, pa[t][1].y);
                __half2 h3 = __floats2half2_rn(pa[t][1].z, pa[t][1].w);
                uint4 u;
                u.x = *(uint32_t*)&h0; u.y = *(uint32_t*)&h1;
                u.z = *(uint32_t*)&h2; u.w = *(uint32_t*)&h3;
                *(uint4*)(Ab0 + nsel * 16384 + aSt[t]) = u;
            }
        }
    }

    float* part = g_attn + (size_t)kHalf * 2097152;
#pragma unroll
    for (int ma = 0; ma < 4; ma++) {
        int r0 = m0 + warp_m + ma * 16 + (lane >> 2);
        int r1 = r0 + 8;
#pragma unroll
        for (int na = 0; na < 8; na++) {
            int col = n0 + warp_n + na * 8 + (lane & 3) * 2;
            *(float2*)(part + (size_t)r0 * 512 + col) = make_float2(c[ma][na][0], c[ma][na][1]);
            *(float2*)(part + (size_t)r1 * 512 + col) = make_float2(c[ma][na][2], c[ma][na][3]);
        }
    }
}

// ============================================================================
// combine split-K partials:  g_x = p0 + p1 + patch_b + pos_emb  (fp32)
// ============================================================================
__global__ void k_patch_sum(const float* __restrict__ pb,
                            const float* __restrict__ pos) {
    int idx = blockIdx.x * blockDim.x + threadIdx.x;
    if (idx >= 4096 * 128) return;
    int row = idx >> 7;
    int c4  = idx & 127;
    int tok = row & 1023;
    float4 a = ((const float4*)g_attn)[idx];
    float4 b = ((const float4*)(g_attn + 2097152))[idx];
    float4 pb4 = ((const float4*)pb)[c4];
    float4 ps  = ((const float4*)pos)[(size_t)tok * 128 + c4];
    float4 o;
    o.x = a.x + b.x + pb4.x + ps.x;
    o.y = a.y + b.y + pb4.y + ps.y;
    o.z = a.z + b.z + pb4.z + ps.z;
    o.w = a.w + b.w + pb4.w + ps.w;
    ((float4*)g_x)[idx] = o;
}

// ============================================================================
// layer GEMM fp16: C = A(half[M][K]) @ W(half[n][K]) (+bias)(+gelu)
// out: fp16 buffer (cIsHalf) or fp32 buffer (+resid)(+tf32 rnd).
// CTA 128x128, 512 thr, warp 32x32, BK=32, cp.async double-buffered.
// ============================================================================
__global__ __launch_bounds__(512, 1)
void k_gemm_h(int aId, int K, u64 bOff,
              int cIsHalf, int cId, int ldC,
              const float* __restrict__ bias, int addResid, int gelu, int rnd) {
    __shared__ __align__(16) char Ab[2][8192];
    __shared__ __align__(16) char Bb[2][8192];

    const int tid  = threadIdx.x;
    const int lane = tid & 31;
    const int wid  = tid >> 5;
    const int warp_m = (wid & 3) * 32;
    const int warp_n = (wid >> 2) * 32;
    const int m0 = blockIdx.y * 128;
    const int n0 = blockIdx.x * 128;

    const __half* A = bufh(aId);
    const __half* Bw = g_wtsh + bOff;

    const int kg = tid & 3;
    const int row = tid >> 2;          // 0..127
    const int sw = (kg ^ ((row >> 1) & 3)) << 4;
    const int stOff = row * 64 + sw;

    const __half* aSrc = A + (size_t)(m0 + row) * K + kg * 8;
    const __half* bSrc = Bw + (size_t)(n0 + row) * K + kg * 8;

    const int kb4 = (lane & 3) * 4;

    float c[2][4][4];
#pragma unroll
    for (int i = 0; i < 2; i++)
#pragma unroll
        for (int j = 0; j < 4; j++)
#pragma unroll
            for (int q = 0; q < 4; q++) c[i][j][q] = 0.0f;

    cpa16(smem_u32(Ab[0] + stOff), aSrc);
    cpa16(smem_u32(Bb[0] + stOff), bSrc);
    cpcommit();

    const int iters = K >> 5;
    for (int it = 0; it < iters; it++) {
        cpwait0();
        __syncthreads();
        const int bsel = it & 1;
        const int nsel = bsel ^ 1;
        if (it < iters - 1) {
            int k0 = (it + 1) * 32;
            cpa16(smem_u32(Ab[nsel] + stOff), aSrc + k0);
            cpa16(smem_u32(Bb[nsel] + stOff), bSrc + k0);
            cpcommit();
        }

        const char* Asb = Ab[bsel];
        const char* Bsb = Bb[bsel];
#pragma unroll
        for (int s = 0; s < 2; s++) {
            const int gl0 = s * 2, gl1 = s * 2 + 1;
            uint32_t af[2][4];
#pragma unroll
            for (int ma = 0; ma < 2; ma++) {
                int r0 = warp_m + ma * 16 + (lane >> 2);
                int r1 = r0 + 8;
                int x0 = (r0 >> 1) & 3, x1 = (r1 >> 1) & 3;
                af[ma][0] = *(const uint32_t*)(Asb + r0 * 64 + ((gl0 ^ x0) << 4) + kb4);
                af[ma][1] = *(const uint32_t*)(Asb + r1 * 64 + ((gl0 ^ x1) << 4) + kb4);
                af[ma][2] = *(const uint32_t*)(Asb + r0 * 64 + ((gl1 ^ x0) << 4) + kb4);
                af[ma][3] = *(const uint32_t*)(Asb + r1 * 64 + ((gl1 ^ x1) << 4) + kb4);
            }
#pragma unroll
            for (int na = 0; na < 4; na++) {
                int n = warp_n + na * 8 + (lane >> 2);
                int xn = (n >> 1) & 3;
                uint32_t b0 = *(const uint32_t*)(Bsb + n * 64 + ((gl0 ^ xn) << 4) + kb4);
                uint32_t b1 = *(const uint32_t*)(Bsb + n * 64 + ((gl1 ^ xn) << 4) + kb4);
#pragma unroll
                for (int ma = 0; ma < 2; ma++)
                    mma16(c[ma][na], af[ma], b0, b1);
            }
        }
    }

#pragma unroll
    for (int ma = 0; ma < 2; ma++) {
        int r0 = m0 + warp_m + ma * 16 + (lane >> 2);
        int r1 = r0 + 8;
#pragma unroll
        for (int na = 0; na < 4; na++) {
            int col = n0 + warp_n + na * 8 + (lane & 3) * 2;
            float v[4] = {c[ma][na][0], c[ma][na][1], c[ma][na][2], c[ma][na][3]};
            if (bias) {
                float b0 = bias[col], b1 = bias[col + 1];
                v[0] += b0; v[1] += b1; v[2] += b0; v[3] += b1;
            }
            if (gelu) {
#pragma unroll
                for (int q = 0; q < 4; q++)
                    v[q] = 0.5f * v[q] * (1.0f + erff(v[q] * 0.70710678118654752f));
            }
            if (cIsHalf) {
                __half* Ch = bufh(cId);
                __half2 h0 = __floats2half2_rn(v[0], v[1]);
                __half2 h1 = __floats2half2_rn(v[2], v[3]);
                *(uint32_t*)(Ch + (size_t)r0 * ldC + col) = *(uint32_t*)&h0;
                *(uint32_t*)(Ch + (size_t)r1 * ldC + col) = *(uint32_t*)&h1;
            } else {
                float* C = buf(cId);
                if (addResid) {
                    v[0] += g_x[(size_t)r0 * 512 + col];
                    v[1] += g_x[(size_t)r0 * 512 + col + 1];
                    v[2] += g_x[(size_t)r1 * 512 + col];
                    v[3] += g_x[(size_t)r1 * 512 + col + 1];
                }
                if (rnd) {
#pragma unroll
                    for (int q = 0; q < 4; q++)
                        v[q] = __uint_as_float(f2tf(v[q]));
                }
                *(float2*)(C + (size_t)r0 * ldC + col) = make_float2(v[0], v[1]);
                *(float2*)(C + (size_t)r1 * ldC + col) = make_float2(v[2], v[3]);
            }
        }
    }
}

// ============================================================================
// out-proj TC GEMM (tf32, cp.async) — validated R11/R14, A fp32
// ============================================================================
template<int BN>
__global__ __launch_bounds__(BN * 4, 1)
void k_tc_nn(int aId, int ldA, u64 bOff, int ldB,
             int cId, int ldC, int K,
             const float* __restrict__ bias, int addResid, int gelu, int rnd) {
    constexpr int NT = BN * 4;
    constexpr int AROWS = NT / 8;
    constexpr int BCH = BN / 4;
    constexpr int BPAD = BN + 8;

    __shared__ __align__(16) float As[2][128 * 32];
    __shared__ __align__(16) float Bs[2][32 * BPAD];

    const int tid  = threadIdx.x;
    const int lane = tid & 31;
    const int wid  = tid >> 5;
    const int warp_m = (wid & 3) * 32;
    const int warp_n = (wid >> 2) * 32;
    const int m0 = blockIdx.y * 128;
    const int n0 = blockIdx.x * BN;

    const float* A = buf(aId);
    const float* Bw = g_wts + bOff;
    float* C = buf(cId);

    const int aq = tid & 7;
    const int am = tid >> 3;
    const int bc = tid % BCH;
    const int bk = tid / BCH;

    const int aw = am * 32 + ((aq ^ (am & 7)) << 2);
    const int bw = bk * BPAD + bc * 4;

    float c[2][4][4];
#pragma unroll
    for (int i = 0; i < 2; i++)
#pragma unroll
        for (int j = 0; j < 4; j++)
#pragma unroll
            for (int q = 0; q < 4; q++) c[i][j][q] = 0.0f;

    {
#pragma unroll
        for (int t = 0; t < 2; t++)
            cpa16(smem_u32(&As[0][aw + t * AROWS * 32]),
                  A + (size_t)(m0 + am + t * AROWS) * ldA + aq * 4);
#pragma unroll
        for (int t = 0; t < 2; t++)
            cpa16(smem_u32(&Bs[0][bw + t * 16 * BPAD]),
                  Bw + (size_t)(bk + t * 16) * ldB + n0 + bc * 4);
        cpcommit();
    }

    const int iters = K >> 5;
    for (int it = 0; it < iters; it++) {
        cpwait0();
        __syncthreads();
        const int bsel = it & 1;
        const int nsel = bsel ^ 1;
        if (it < iters - 1) {
            int k0 = (it + 1) * 32;
#pragma unroll
            for (int t = 0; t < 2; t++)
                cpa16(smem_u32(&As[nsel][aw + t * AROWS * 32]),
                      A + (size_t)(m0 + am + t * AROWS) * ldA + k0 + aq * 4);
#pragma unroll
            for (int t = 0; t < 2; t++)
                cpa16(smem_u32(&Bs[nsel][bw + t * 16 * BPAD]),
                      Bw + (size_t)(k0 + bk + t * 16) * ldB + n0 + bc * 4);
            cpcommit();
        }

        const float* Asb = As[bsel];
        const float* Bsb = Bs[bsel];
#pragma unroll
        for (int kk = 0; kk < 4; kk++) {
            uint32_t af[2][4], bf[4][2];
            const int kq0 = kk * 2, kq1 = kk * 2 + 1;
            const int kb  = lane & 3;
#pragma unroll
            for (int ma = 0; ma < 2; ma++) {
                int r0 = warp_m + ma * 16 + (lane >> 2);
                int r1 = r0 + 8;
                af[ma][0] = ldu(&Asb[r0 * 32 + ((kq0 ^ (r0 & 7)) << 2) + kb]);
                af[ma][1] = ldu(&Asb[r1 * 32 + ((kq0 ^ (r1 & 7)) << 2) + kb]);
                af[ma][2] = ldu(&Asb[r0 * 32 + ((kq1 ^ (r0 & 7)) << 2) + kb]);
                af[ma][3] = ldu(&Asb[r1 * 32 + ((kq1 ^ (r1 & 7)) << 2) + kb]);
            }
#pragma unroll
            for (int na = 0; na < 4; na++) {
                int n = warp_n + na * 8 + (lane >> 2);
                bf[na][0] = ldu(&Bsb[(kk * 8 + kb) * BPAD + n]);
                bf[na][1] = ldu(&Bsb[(kk * 8 + 4 + kb) * BPAD + n]);
            }
#pragma unroll
            for (int ma = 0; ma < 2; ma++)
#pragma unroll
                for (int na = 0; na < 4; na++)
                    mma8(c[ma][na], af[ma], bf[na][0], bf[na][1]);
        }
    }

#pragma unroll
    for (int ma = 0; ma < 2; ma++) {
        int r0 = m0 + warp_m + ma * 16 + (lane >> 2);
        int r1 = r0 + 8;
#pragma unroll
        for (int na = 0; na < 4; na++) {
            int col = n0 + warp_n + na * 8 + (lane & 3) * 2;
            float v[4] = {c[ma][na][0], c[ma][na][1], c[ma][na][2], c[ma][na][3]};
            if (bias) {
                float b0 = bias[col], b1 = bias[col + 1];
                v[0] += b0; v[1] += b1; v[2] += b0; v[3] += b1;
            }
            if (gelu) {
#pragma unroll
                for (int q = 0; q < 4; q++)
                    v[q] = 0.5f * v[q] * (1.0f + erff(v[q] * 0.70710678118654752f));
            }
            if (addResid) {
                v[0] += g_x[(size_t)r0 * 512 + col];
                v[1] += g_x[(size_t)r0 * 512 + col + 1];
                v[2] += g_x[(size_t)r1 * 512 + col];
                v[3] += g_x[(size_t)r1 * 512 + col + 1];
            }
            if (rnd) {
#pragma unroll
                for (int q = 0; q < 4; q++)
                    v[q] = __uint_as_float(f2tf(v[q]));
            }
            *(float2*)(C + (size_t)r0 * ldC + col) = make_float2(v[0], v[1]);
            *(float2*)(C + (size_t)r1 * ldC + col) = make_float2(v[2], v[3]);
        }
    }
}

// ============================================================================
// FUSED attention (FlashAttention-2 style, tf32) — R12/R14 validated
// ============================================================================
__global__ __launch_bounds__(256, 1)
void k_attn_fused(const float* __restrict__ tbl, int qkvld, int inner, int hc) {
    extern __shared__ float sm[];
    float* Qs = sm;
    float* Ks = sm + 8192;
    float* Vs = sm + 8192 + 8704;
    float* Ps = sm + 8192 + 8704 + 9216;

    const int tid  = threadIdx.x;
    const int lane = tid & 31;
    const int wid  = tid >> 5;
    const int i0 = blockIdx.x * 128;
    const int z  = blockIdx.y;
    const int bb = z / hc, head = z % hc;
    const float* Qb = g_qkv + (size_t)bb * 1024 * qkvld + head * 64;
    const float* Kb = Qb + inner;
    const float* Vb = Qb + 2 * inner;

    {
        const int aq = tid & 15;
        const int am = tid >> 4;
#pragma unroll
        for (int t = 0; t < 8; t++) {
            int m = am + t * 16;
            float4 v = *(const float4*)(Qb + (size_t)(i0 + m) * qkvld + aq * 4);
            int p = (aq & 8) | ((aq ^ (m & 7)) & 7);
            *(float4*)&Qs[m * 64 + (p << 2)] = v;
        }
    }

    const int rl0 = wid * 16 + (lane >> 2);
    const int rl1 = rl0 + 8;
    const int gr0 = i0 + rl0, gr1 = i0 + rl1;
    const int ih0 = gr0 >> 5, iw0 = gr0 & 31;
    const int ih1 = gr1 >> 5, iw1 = gr1 & 31;
    const int kb  = lane & 3;

    float o[8][4];
#pragma unroll
    for (int j = 0; j < 8; j++) { o[j][0] = o[j][1] = o[j][2] = o[j][3] = 0.f; }
    float m0 = -1e30f, m1 = -1e30f, l0 = 0.f, l1 = 0.f;

    for (int jt = 0; jt < 8; jt++) {
        const int j0 = jt * 128;
        __syncthreads();
        {
            const int n = tid & 127;
            const int cc = tid >> 7;
#pragma unroll
            for (int t = 0; t < 8; t++) {
                int kq = cc + t * 2;
                float4 v = *(const float4*)(Kb + (size_t)(j0 + n) * qkvld + kq * 4);
                Ks[(kq * 4 + 0) * 136 + n] = v.x;
                Ks[(kq * 4 + 1) * 136 + n] = v.y;
                Ks[(kq * 4 + 2) * 136 + n] = v.z;
                Ks[(kq * 4 + 3) * 136 + n] = v.w;
            }
        }
        {
#pragma unroll
            for (int t = 0; t < 8; t++) {
                int idx = tid + t * 256;
                int row = idx >> 4, c4 = idx & 15;
                float4 v = *(const float4*)(Vb + (size_t)(j0 + row) * qkvld + c4 * 4);
                *(float4*)&Vs[row * 72 + c4 * 4] = v;
            }
        }
        __syncthreads();

        float s[16][4];
#pragma unroll
        for (int na = 0; na < 16; na++) { s[na][0] = s[na][1] = s[na][2] = s[na][3] = 0.f; }
#pragma unroll
        for (int kk = 0; kk < 8; kk++) {
            uint32_t af[4];
            int kq0 = kk * 2, kq1 = kk * 2 + 1;
            int p00 = (kq0 & 8) | ((kq0 ^ (rl0 & 7)) & 7);
            int p01 = (kq0 & 8) | ((kq0 ^ (rl1 & 7)) & 7);
            int p10 = (kq1 & 8) | ((kq1 ^ (rl0 & 7)) & 7);
            int p11 = (kq1 & 8) | ((kq1 ^ (rl1 & 7)) & 7);
            af[0] = ldu(&Qs[rl0 * 64 + (p00 << 2) + kb]);
            af[1] = ldu(&Qs[rl1 * 64 + (p01 << 2) + kb]);
            af[2] = ldu(&Qs[rl0 * 64 + (p10 << 2) + kb]);
            af[3] = ldu(&Qs[rl1 * 64 + (p11 << 2) + kb]);
#pragma unroll
            for (int na = 0; na < 16; na++) {
                int n = na * 8 + (lane >> 2);
                uint32_t b0 = ldu(&Ks[(kk * 8 + kb) * 136 + n]);
                uint32_t b1 = ldu(&Ks[(kk * 8 + 4 + kb) * 136 + n]);
                mma8(s[na], af, b0, b1);
            }
        }
#pragma unroll
        for (int na = 0; na < 16; na++) {
            int jj = j0 + na * 8 + (lane & 3) * 2;
            int jh0 = jj >> 5, jw0 = jj & 31;
            int jh1 = (jj + 1) >> 5, jw1 = (jj + 1) & 31;
            s[na][0] = s[na][0] * 0.125f + tbl[(size_t)((ih0 - jh0 + 31) * 63 + (iw0 - jw0 + 31)) * hc + head];
            s[na][1] = s[na][1] * 0.125f + tbl[(size_t)((ih0 - jh1 + 31) * 63 + (iw0 - jw1 + 31)) * hc + head];
            s[na][2] = s[na][2] * 0.125f + tbl[(size_t)((ih1 - jh0 + 31) * 63 + (iw1 - jw0 + 31)) * hc + head];
            s[na][3] = s[na][3] * 0.125f + tbl[(size_t)((ih1 - jh1 + 31) * 63 + (iw1 - jw1 + 31)) * hc + head];
        }
        float mx0 = -1e30f, mx1 = -1e30f;
#pragma unroll
        for (int na = 0; na < 16; na++) {
            mx0 = fmaxf(mx0, fmaxf(s[na][0], s[na][1]));
            mx1 = fmaxf(mx1, fmaxf(s[na][2], s[na][3]));
        }
        mx0 = fmaxf(mx0, __shfl_xor_sync(0xffffffffu, mx0, 1));
        mx0 = fmaxf(mx0, __shfl_xor_sync(0xffffffffu, mx0, 2));
        mx1 = fmaxf(mx1, __shfl_xor_sync(0xffffffffu, mx1, 1));
        mx1 = fmaxf(mx1, __shfl_xor_sync(0xffffffffu, mx1, 2));
        float mn0 = fmaxf(m0, mx0), mn1 = fmaxf(m1, mx1);
        float al0 = __expf(m0 - mn0), al1 = __expf(m1 - mn1);
        float ls0 = 0.f, ls1 = 0.f;
#pragma unroll
        for (int na = 0; na < 16; na++) {
            s[na][0] = __expf(s[na][0] - mn0);
            s[na][1] = __expf(s[na][1] - mn0);
            s[na][2] = __expf(s[na][2] - mn1);
            s[na][3] = __expf(s[na][3] - mn1);
            ls0 += s[na][0] + s[na][1];
            ls1 += s[na][2] + s[na][3];
        }
        ls0 += __shfl_xor_sync(0xffffffffu, ls0, 1);
        ls0 += __shfl_xor_sync(0xffffffffu, ls0, 2);
        ls1 += __shfl_xor_sync(0xffffffffu, ls1, 1);
        ls1 += __shfl_xor_sync(0xffffffffu, ls1, 2);
        l0 = l0 * al0 + ls0;
        l1 = l1 * al1 + ls1;
        m0 = mn0; m1 = mn1;
#pragma unroll
        for (int j = 0; j < 8; j++) {
            o[j][0] *= al0; o[j][1] *= al0; o[j][2] *= al1; o[j][3] *= al1;
        }
#pragma unroll
        for (int na = 0; na < 16; na++) {
            int c = na * 8 + (lane & 3) * 2;
            int g = c >> 2;
            int a0 = rl0 * 128 + ((g ^ (rl0 & 7)) << 2) + (c & 3);
            int a1 = rl1 * 128 + ((g ^ (rl1 & 7)) << 2) + (c & 3);
            Ps[a0]     = __uint_as_float(f2tf(s[na][0]));
            Ps[a0 + 1] = __uint_as_float(f2tf(s[na][1]));
            Ps[a1]     = __uint_as_float(f2tf(s[na][2]));
            Ps[a1 + 1] = __uint_as_float(f2tf(s[na][3]));
        }
        __syncthreads();
#pragma unroll
        for (int kk = 0; kk < 16; kk++) {
            uint32_t af[4];
            int g0 = kk * 2, g1 = kk * 2 + 1;
            af[0] = ldu(&Ps[rl0 * 128 + ((g0 ^ (rl0 & 7)) << 2) + kb]);
            af[1] = ldu(&Ps[rl1 * 128 + ((g0 ^ (rl1 & 7)) << 2) + kb]);
            af[2] = ldu(&Ps[rl0 * 128 + ((g1 ^ (rl0 & 7)) << 2) + kb]);
            af[3] = ldu(&Ps[rl1 * 128 + ((g1 ^ (rl1 & 7)) << 2) + kb]);
#pragma unroll
            for (int na = 0; na < 8; na++) {
                int n = na * 8 + (lane >> 2);
                uint32_t b0 = ldu(&Vs[(kk * 8 + kb) * 72 + n]);
                uint32_t b1 = ldu(&Vs[(kk * 8 + 4 + kb) * 72 + n]);
                mma8(o[na], af, b0, b1);
            }
        }
    }

    float inv0 = 1.0f / l0, inv1 = 1.0f / l1;
    float* Ob = g_o + ((size_t)bb * 1024) * inner + head * 64;
#pragma unroll
    for (int na = 0; na < 8; na++) {
        int col = na * 8 + (lane & 3) * 2;
        float2 w0 = make_float2(__uint_as_float(f2tf(o[na][0] * inv0)),
                                __uint_as_float(f2tf(o[na][1] * inv0)));
        float2 w1 = make_float2(__uint_as_float(f2tf(o[na][2] * inv1)),
                                __uint_as_float(f2tf(o[na][3] * inv1)));
        *(float2*)(Ob + (size_t)gr0 * inner + col) = w0;
        *(float2*)(Ob + (size_t)gr1 * inner + col) = w1;
    }
}

// ============================================================================
// LayerNorm over 512 — warp-per-row, output fp16 g_xnh
// ============================================================================
__global__ void k_layernorm(const float* __restrict__ s, const float* __restrict__ b) {
    int tid  = threadIdx.x;
    int lane = tid & 31;
    int row  = blockIdx.x * 4 + (tid >> 5);
    const float4* rp = (const float4*)(g_x + (size_t)row * 512);
    float4 v[4];
    float sum = 0.f, sq = 0.f;
#pragma unroll
    for (int q = 0; q < 4; q++) {
        v[q] = rp[lane + 32 * q];
        sum += v[q].x + v[q].y + v[q].z + v[q].w;
        sq  += v[q].x * v[q].x + v[q].y * v[q].y + v[q].z * v[q].z + v[q].w * v[q].w;
    }
#pragma unroll
    for (int o = 16; o; o >>= 1) {
        sum += __shfl_xor_sync(0xffffffffu, sum, o);
        sq  += __shfl_xor_sync(0xffffffffu, sq, o);
    }
    float mean = sum * (1.0f / 512.0f);
    float var  = sq * (1.0f / 512.0f) - mean * mean;
    float rstd = rsqrtf(var + 1e-5f);
#pragma unroll
    for (int q = 0; q < 4; q++) {
        int c4 = lane + 32 * q;
        float4 sv = ((const float4*)s)[c4];
        float4 bv = ((const float4*)b)[c4];
        __half2 h0 = __floats2half2_rn((v[q].x - mean) * rstd * sv.x + bv.x,
                                       (v[q].y - mean) * rstd * sv.y + bv.y);
        __half2 h1 = __floats2half2_rn((v[q].z - mean) * rstd * sv.z + bv.z,
                                       (v[q].w - mean) * rstd * sv.w + bv.w);
        uint2 u; u.x = *(uint32_t*)&h0; u.y = *(uint32_t*)&h1;
        *(uint2*)(g_xnh + (size_t)row * 512 + c4 * 4) = u;
    }
}

// ============================================================================
// final layout: out[b][d][n] = g_x[b][n][d]
// ============================================================================
__global__ void k_out(float* __restrict__ out) {
    __shared__ float t[32][33];
    int bb = blockIdx.z;
    int n0 = blockIdx.x * 32, d0 = blockIdx.y * 32;
    int tx = threadIdx.x, ty = threadIdx.y;
#pragma unroll
    for (int i = 0; i < 32; i += 8)
        t[ty + i][tx] = g_x[((size_t)bb * 1024 + n0 + ty + i) * 512 + d0 + tx];
    __syncthreads();
#pragma unroll
    for (int i = 0; i < 32; i += 8)
        out[((size_t)bb * 512 + d0 + ty + i) * 1024 + n0 + tx] = t[tx][ty + i];
}

// ============================================================================
// host orchestration
// ============================================================================
extern "C" void kernel_launch(void* const* d_in, const int* in_sizes, int n_in,
                              void* d_out, int out_size) {
    const float *img = 0, *patch_w = 0, *patch_b = 0, *pos_emb = 0;
    const float *ln1_s = 0, *ln1_b = 0, *ln2_s = 0, *ln2_b = 0;
    const float *qkv_w[3] = {0, 0, 0}, *out_w[3] = {0, 0, 0}, *out_b[3] = {0, 0, 0};
    const float *tbl[3] = {0, 0, 0};
    const float *ff_w1 = 0, *ff_b1 = 0, *ff_w2 = 0, *ff_b2 = 0;
    int c512 = 0, c1536 = 0, c393 = 0;
    for (int i = 0; i < n_in; i++) {
        const float* p = (const float*)d_in[i];
        switch (in_sizes[i]) {
            case 134217728: img = p; break;
            case 16777216: patch_w = p; break;
            case 524288:   pos_emb = p; break;
            case 512: {
                const float** t[4] = {&patch_b, &out_b[0], &out_b[1], &out_b[2]};
                if (c512 < 4) *t[c512] = p;
                c512++;
            } break;
            case 1536: {
                const float** t[5] = {&ln1_s, &ln1_b, &ln2_s, &ln2_b, &ff_b2};
                if (c1536 < 5) *t[c1536] = p;
                c1536++;
            } break;
            case 768:    ff_b1 = p; break;
            case 196608: qkv_w[0] = p; break;
            case 393216: {
                const float** t[3] = {&qkv_w[1], &ff_w1, &ff_w2};
                if (c393 < 3) *t[c393] = p;
                c393++;
            } break;
            case 786432: qkv_w[2] = p; break;
            case 65536:  out_w[0] = p; break;
            case 131072: out_w[1] = p; break;
            case 262144: out_w[2] = p; break;
            case 7938:   tbl[0] = p; break;
            case 15876:  tbl[1] = p; break;
            case 31752:  tbl[2] = p; break;
            default: break;
        }
    }

    bool ok = img && patch_w && patch_b && pos_emb && ln1_s && ln1_b && ln2_s &&
              ln2_b && ff_w1 && ff_b1 && ff_w2 && ff_b2;
    for (int l = 0; l < 3; l++)
        ok = ok && qkv_w[l] && out_w[l] && out_b[l] && tbl[l];
    if (!ok) {
        k_zero<<<(out_size + 255) / 256, 256>>>((float*)d_out, out_size);
        return;
    }

    const int PATCH_SMEM = 32768 + 16384;                    // 49152 B
    const int ATT_SMEM   = (8192 + 8704 + 9216 + 16384) * 4; // 169984 B
    cudaFuncSetAttribute(k_patch_h,
                         cudaFuncAttributeMaxDynamicSharedMemorySize, PATCH_SMEM);
    cudaFuncSetAttribute(k_attn_fused,
                         cudaFuncAttributeMaxDynamicSharedMemorySize, ATT_SMEM);

    k_permute_pw<<<(4096 * 512 + 255) / 256, 256>>>(patch_w);
    k_patch_h<<<dim3(4, 16, 2), 256, PATCH_SMEM>>>(img);
    k_patch_sum<<<(4096 * 128 + 255) / 256, 256>>>(patch_b, pos_emb);

    // ---- out_w -> tf32 g_wts (one launch) ----
    const u64 OUTW_OFF[3] = {0ULL, 65536ULL, 196608ULL};
    {
        CvtJobs j;
        int n4s[3] = {16384, 32768, 65536};
        int cum = 0;
        for (int i = 0; i < 3; i++) {
            j.src[i] = out_w[i]; j.dst[i] = OUTW_OFF[i]; j.cum[i] = cum; cum += n4s[i];
        }
        j.cum[3] = cum;
        k_cvt_all<<<(cum + 255) / 256, 256>>>(j);
    }

    // ---- qkv/ff1/ff2 -> fp16 [n][K] g_wtsh (one launch) ----
    const u64 QKVH_OFF[3] = {0ULL, 196608ULL, 589824ULL};
    const u64 FF1H_OFF = 1376256ULL;   // + l*131072
    const u64 FF2H_OFF = 1769472ULL;   // + l*131072
    {
        TJobs j;
        const float* srcs[9] = {qkv_w[0], qkv_w[1], qkv_w[2],
                                ff_w1, ff_w1 + 131072, ff_w1 + 262144,
                                ff_w2, ff_w2 + 131072, ff_w2 + 262144};
        u64 dsts[9] = {QKVH_OFF[0], QKVH_OFF[1], QKVH_OFF[2],
                       FF1H_OFF, FF1H_OFF + 131072, FF1H_OFF + 262144,
                       FF2H_OFF, FF2H_OFF + 131072, FF2H_OFF + 262144};
        int Ks[9] = {512, 512, 512, 512, 512, 512, 256, 256, 256};
        int Ns[9] = {384, 768, 1536, 256, 256, 256, 512, 512, 512};
        int cum = 0;
        for (int i = 0; i < 9; i++) {
            j.src[i] = srcs[i]; j.dst[i] = dsts[i];
            j.K[i] = Ks[i]; j.N[i] = Ns[i]; j.cum[i] = cum;
            cum += (Ks[i] >> 3) * Ns[i];
        }
        j.cum[9] = cum;
        k_cvt_t_all<<<(cum + 255) / 256, 256>>>(j);
    }

    const int heads[3] = {2, 4, 8};
    for (int l = 0; l < 3; l++) {
        int h = heads[l];
        int inner = 64 * h;
        int qkvld = 3 * inner;

        // ---- attention ----
        k_layernorm<<<1024, 128>>>(ln1_s + l * 512, ln1_b + l * 512);
        k_gemm_h<<<dim3(qkvld / 128, 32), 512>>>(
            HBUF_XN, 512, QKVH_OFF[l], 0, BUF_QKV, qkvld, nullptr, 0, 0, 1);
        k_attn_fused<<<dim3(8, 4 * h), 256, ATT_SMEM>>>(tbl[l], qkvld, inner, h);
        k_tc_nn<128><<<dim3(4, 32), 512>>>(
            BUF_O, inner, OUTW_OFF[l], 512, BUF_X, 512, inner,
            out_b[l], 1, 0, 0);

        // ---- feed-forward ----
        k_layernorm<<<1024, 128>>>(ln2_s + l * 512, ln2_b + l * 512);
        k_gemm_h<<<dim3(2, 32), 512>>>(
            HBUF_XN, 512, FF1H_OFF + (u64)l * 131072, 1, HBUF_H, 256,
            ff_b1 + l * 256, 0, 1, 0);
        k_gemm_h<<<dim3(4, 32), 512>>>(
            HBUF_H, 256, FF2H_OFF + (u64)l * 131072, 0, BUF_X, 512,
            ff_b2 + l * 512, 1, 0, 0);
    }

    k_out<<<dim3(32, 16, 4), dim3(32, 8)>>>((float*)d_out);
}

// round 16
// speedup vs baseline: 1.4842x; 1.0178x over previous
#include <cuda_runtime.h>
#include <cuda_fp16.h>
#include <math.h>
#include <stdint.h>

typedef unsigned long long u64;

// ---------------- problem constants ----------------
// B=4, C=128, H=W=512, P=16, GH=GW=32, N=1024, PATCH_DIM=32768, DIM=512,
// MLP=256, DH=64, HEADS=(2,4,8), NUM_REL=3969

// ---------------- scratch (device globals) ----------------
__device__ __align__(16) __half g_pw2h[32768 * 512]; // patch_w fp16 [d][k']
__device__ __align__(16) float  g_x[4096 * 512];     // residual stream (fp32)
__device__ __align__(16) float  g_qkv[4096 * 1536];  // qkv (fp32, tf32-rounded)
__device__ __align__(16) float  g_attn[4194304];     // patch split-K partials
__device__ __align__(16) __half g_xnh[4096 * 512];   // LN output fp16
__device__ __align__(16) __half g_oh[4096 * 512];    // attention out fp16
__device__ __align__(16) __half g_hh[4096 * 256];    // FFN hidden fp16
__device__ __align__(16) __half g_wtsh[2621440];     // fp16 weights [n][K]

#define BUF_X   0
#define BUF_QKV 1
__device__ __forceinline__ float* buf(int id) {
    return id == BUF_X ? g_x : g_qkv;
}
#define HBUF_XN 0
#define HBUF_H  1
#define HBUF_O  2
__device__ __forceinline__ __half* bufh(int id) {
    switch (id) {
        case HBUF_XN: return g_xnh;
        case HBUF_H:  return g_hh;
        default:      return g_oh;
    }
}

// ============================================================================
__global__ void k_zero(float* o, int n) {
    int i = blockIdx.x * blockDim.x + threadIdx.x;
    if (i < n) o[i] = 0.0f;
}

// ============================================================================
// helpers
// ============================================================================
__device__ __forceinline__ uint32_t f2tf(float f) {
    uint32_t r;
    asm("cvt.rna.tf32.f32 %0, %1;" : "=r"(r) : "f"(f));
    return r;
}
__device__ __forceinline__ void mma8(float* c, const uint32_t* a,
                                     uint32_t b0, uint32_t b1) {
    asm("mma.sync.aligned.m16n8k8.row.col.f32.tf32.tf32.f32 "
        "{%0,%1,%2,%3},{%4,%5,%6,%7},{%8,%9},{%0,%1,%2,%3};"
        : "+f"(c[0]), "+f"(c[1]), "+f"(c[2]), "+f"(c[3])
        : "r"(a[0]), "r"(a[1]), "r"(a[2]), "r"(a[3]), "r"(b0), "r"(b1));
}
__device__ __forceinline__ void mma16(float* c, const uint32_t* a,
                                      uint32_t b0, uint32_t b1) {
    asm("mma.sync.aligned.m16n8k16.row.col.f32.f16.f16.f32 "
        "{%0,%1,%2,%3},{%4,%5,%6,%7},{%8,%9},{%0,%1,%2,%3};"
        : "+f"(c[0]), "+f"(c[1]), "+f"(c[2]), "+f"(c[3])
        : "r"(a[0]), "r"(a[1]), "r"(a[2]), "r"(a[3]), "r"(b0), "r"(b1));
}
__device__ __forceinline__ uint32_t ldu(const float* p) {
    return __float_as_uint(*p);
}
__device__ __forceinline__ uint32_t smem_u32(const void* p) {
    return (uint32_t)__cvta_generic_to_shared(p);
}
__device__ __forceinline__ void cpa16(uint32_t s, const void* g) {
    asm volatile("cp.async.cg.shared.global [%0], [%1], 16;" :: "r"(s), "l"(g));
}
__device__ __forceinline__ void cpcommit() {
    asm volatile("cp.async.commit_group;");
}
__device__ __forceinline__ void cpwait0() {
    asm volatile("cp.async.wait_group 0;" ::: "memory");
}

// ============================================================================
// permute patch_w to fp16 [d][k']
// ============================================================================
__global__ void k_permute_pw(const float* __restrict__ pw) {
    int idx = blockIdx.x * blockDim.x + threadIdx.x;   // 4096 * 512
    if (idx >= 4096 * 512) return;
    int k8 = idx >> 9;
    int d  = idx & 511;
    int kp = k8 * 8;
    int c  = kp >> 8;
    int p  = kp & 255;
    __half2 h[4];
#pragma unroll
    for (int i = 0; i < 4; i++) {
        float v0 = pw[(size_t)((p + 2 * i) * 128 + c) * 512 + d];
        float v1 = pw[(size_t)((p + 2 * i + 1) * 128 + c) * 512 + d];
        h[i] = __floats2half2_rn(v0, v1);
    }
    uint4 u;
    u.x = *(uint32_t*)&h[0]; u.y = *(uint32_t*)&h[1];
    u.z = *(uint32_t*)&h[2]; u.w = *(uint32_t*)&h[3];
    *(uint4*)&g_pw2h[(size_t)d * 32768 + kp] = u;
}

// ============================================================================
// batched fp16 weight transpose [K][N] -> g_wtsh[dst + n*K + k] (12 segments)
// element = one (k8, n): 8 k-values
// ============================================================================
struct TJobs {
    const float* src[12];
    u64 dst[12];
    int K[12];
    int N[12];
    int cum[13];
};
__global__ void k_cvt_t_all(TJobs jobs) {
    int i = blockIdx.x * blockDim.x + threadIdx.x;
    if (i >= jobs.cum[12]) return;
    int s = 0;
#pragma unroll
    for (int t = 1; t < 12; t++) s += (i >= jobs.cum[t]);
    int loc = i - jobs.cum[s];
    int N = jobs.N[s], K = jobs.K[s];
    int n  = loc % N;
    int k  = (loc / N) * 8;
    const float* src = jobs.src[s];
    __half2 h[4];
#pragma unroll
    for (int q = 0; q < 4; q++) {
        float v0 = src[(size_t)(k + 2 * q) * N + n];
        float v1 = src[(size_t)(k + 2 * q + 1) * N + n];
        h[q] = __floats2half2_rn(v0, v1);
    }
    uint4 u;
    u.x = *(uint32_t*)&h[0]; u.y = *(uint32_t*)&h[1];
    u.z = *(uint32_t*)&h[2]; u.w = *(uint32_t*)&h[3];
    *(uint4*)&g_wtsh[jobs.dst[s] + (size_t)n * K + k] = u;
}

// ============================================================================
// patch embed GEMM, split-K partials — fp16 m16n8k16 (R12 validated)
// ============================================================================
__global__ __launch_bounds__(256, 1)
void k_patch_h(const float* __restrict__ img) {
    extern __shared__ char smc[];
    char* Ab0 = smc;
    char* Bb0 = smc + 32768;

    const int tid  = threadIdx.x;
    const int lane = tid & 31;
    const int wid  = tid >> 5;
    const int warp_m = (wid & 3) * 64;
    const int warp_n = (wid >> 2) * 64;
    const int m0 = blockIdx.y * 256;
    const int n0 = blockIdx.x * 128;
    const int kHalf = blockIdx.z;
    const int kBase = kHalf * 16384;

    const int kg = tid & 3;
    const int am = tid >> 2;
    const float* abase[4];
#pragma unroll
    for (int t = 0; t < 4; t++) {
        int m_g = m0 + am + t * 64;
        int bb  = m_g >> 10;
        int tok = m_g & 1023;
        int gh = tok >> 5, gw = tok & 31;
        abase[t] = img + (size_t)bb * 33554432 + (size_t)(gh * 16) * 512 + gw * 16;
    }
    const int bn = tid >> 2;
    const __half* bbase[2];
#pragma unroll
    for (int t = 0; t < 2; t++)
        bbase[t] = g_pw2h + (size_t)(n0 + bn + t * 64) * 32768 + kg * 8;

    const int aSw = (kg ^ ((am >> 1) & 3)) << 4;
    const int bSw = (kg ^ ((bn >> 1) & 3)) << 4;
    int aSt[4], bSt[2];
#pragma unroll
    for (int t = 0; t < 4; t++) aSt[t] = (am + 64 * t) * 64 + aSw;
#pragma unroll
    for (int t = 0; t < 2; t++) bSt[t] = (bn + 64 * t) * 64 + bSw;

    const int kb4 = (lane & 3) * 4;

    float c[4][8][4];
#pragma unroll
    for (int i = 0; i < 4; i++)
#pragma unroll
        for (int j = 0; j < 8; j++)
#pragma unroll
            for (int q = 0; q < 4; q++) c[i][j][q] = 0.0f;

    float4 pa[4][2];

    {
        int k = kBase + kg * 8;
        int cc = k >> 8, rem = k & 255;
        const size_t aoff = (size_t)cc * 262144 + (rem >> 4) * 512 + (rem & 15);
#pragma unroll
        for (int t = 0; t < 4; t++) {
            pa[t][0] = *(const float4*)(abase[t] + aoff);
            pa[t][1] = *(const float4*)(abase[t] + aoff + 4);
        }
#pragma unroll
        for (int t = 0; t < 2; t++)
            cpa16(smem_u32(Bb0 + bSt[t]), bbase[t] + kBase);
        cpcommit();
#pragma unroll
        for (int t = 0; t < 4; t++) {
            __half2 h0 = __floats2half2_rn(pa[t][0].x, pa[t][0].y);
            __half2 h1 = __floats2half2_rn(pa[t][0].z, pa[t][0].w);
            __half2 h2 = __floats2half2_rn(pa[t][1].x, pa[t][1].y);
            __half2 h3 = __floats2half2_rn(pa[t][1].z, pa[t][1].w);
            uint4 u;
            u.x = *(uint32_t*)&h0; u.y = *(uint32_t*)&h1;
            u.z = *(uint32_t*)&h2; u.w = *(uint32_t*)&h3;
            *(uint4*)(Ab0 + aSt[t]) = u;
        }
    }

    for (int it = 0; it < 512; it++) {
        if (it < 511) {
            int k = kBase + (it + 1) * 32 + kg * 8;
            int cc = k >> 8, rem = k & 255;
            const size_t aoff = (size_t)cc * 262144 + (rem >> 4) * 512 + (rem & 15);
#pragma unroll
            for (int t = 0; t < 4; t++) {
                pa[t][0] = *(const float4*)(abase[t] + aoff);
                pa[t][1] = *(const float4*)(abase[t] + aoff + 4);
            }
        }
        cpwait0();
        __syncthreads();
        const int bsel = it & 1;
        const int nsel = bsel ^ 1;
        if (it < 511) {
            int kNext = kBase + (it + 1) * 32;
#pragma unroll
            for (int t = 0; t < 2; t++)
                cpa16(smem_u32(Bb0 + nsel * 8192 + bSt[t]), bbase[t] + kNext);
            cpcommit();
        }

        const char* Asb = Ab0 + bsel * 16384;
        const char* Bsb = Bb0 + bsel * 8192;
#pragma unroll
        for (int s = 0; s < 2; s++) {
            const int gl0 = s * 2, gl1 = s * 2 + 1;
            uint32_t af[4][4];
#pragma unroll
            for (int ma = 0; ma < 4; ma++) {
                int r0 = warp_m + ma * 16 + (lane >> 2);
                int r1 = r0 + 8;
                int x0 = (r0 >> 1) & 3, x1 = (r1 >> 1) & 3;
                af[ma][0] = *(const uint32_t*)(Asb + r0 * 64 + ((gl0 ^ x0) << 4) + kb4);
                af[ma][1] = *(const uint32_t*)(Asb + r1 * 64 + ((gl0 ^ x1) << 4) + kb4);
                af[ma][2] = *(const uint32_t*)(Asb + r0 * 64 + ((gl1 ^ x0) << 4) + kb4);
                af[ma][3] = *(const uint32_t*)(Asb + r1 * 64 + ((gl1 ^ x1) << 4) + kb4);
            }
#pragma unroll
            for (int na = 0; na < 8; na++) {
                int n = warp_n + na * 8 + (lane >> 2);
                int xn = (n >> 1) & 3;
                uint32_t b0 = *(const uint32_t*)(Bsb + n * 64 + ((gl0 ^ xn) << 4) + kb4);
                uint32_t b1 = *(const uint32_t*)(Bsb + n * 64 + ((gl1 ^ xn) << 4) + kb4);
#pragma unroll
                for (int ma = 0; ma < 4; ma++)
                    mma16(c[ma][na], af[ma], b0, b1);
            }
        }

        if (it < 511) {
#pragma unroll
            for (int t = 0; t < 4; t++) {
                __half2 h0 = __floats2half2_rn(pa[t][0].x, pa[t][0].y);
                __half2 h1 = __floats2half2_rn(pa[t][0].z, pa[t][0].w);
                __half2 h2 = __floats2half2_rn(pa[t][1].x, pa[t][1].y);
                __half2 h3 = __floats2half2_rn(pa[t][1].z, pa[t][1].w);
                uint4 u;
                u.x = *(uint32_t*)&h0; u.y = *(uint32_t*)&h1;
                u.z = *(uint32_t*)&h2; u.w = *(uint32_t*)&h3;
                *(uint4*)(Ab0 + nsel * 16384 + aSt[t]) = u;
            }
        }
    }

    float* part = g_attn + (size_t)kHalf * 2097152;
#pragma unroll
    for (int ma = 0; ma < 4; ma++) {
        int r0 = m0 + warp_m + ma * 16 + (lane >> 2);
        int r1 = r0 + 8;
#pragma unroll
        for (int na = 0; na < 8; na++) {
            int col = n0 + warp_n + na * 8 + (lane & 3) * 2;
            *(float2*)(part + (size_t)r0 * 512 + col) = make_float2(c[ma][na][0], c[ma][na][1]);
            *(float2*)(part + (size_t)r1 * 512 + col) = make_float2(c[ma][na][2], c[ma][na][3]);
        }
    }
}

// ============================================================================
// combine split-K partials:  g_x = p0 + p1 + patch_b + pos_emb  (fp32)
// ============================================================================
__global__ void k_patch_sum(const float* __restrict__ pb,
                            const float* __restrict__ pos) {
    int idx = blockIdx.x * blockDim.x + threadIdx.x;
    if (idx >= 4096 * 128) return;
    int row = idx >> 7;
    int c4  = idx & 127;
    int tok = row & 1023;
    float4 a = ((const float4*)g_attn)[idx];
    float4 b = ((const float4*)(g_attn + 2097152))[idx];
    float4 pb4 = ((const float4*)pb)[c4];
    float4 ps  = ((const float4*)pos)[(size_t)tok * 128 + c4];
    float4 o;
    o.x = a.x + b.x + pb4.x + ps.x;
    o.y = a.y + b.y + pb4.y + ps.y;
    o.z = a.z + b.z + pb4.z + ps.z;
    o.w = a.w + b.w + pb4.w + ps.w;
    ((float4*)g_x)[idx] = o;
}

// ============================================================================
// layer GEMM fp16: C = A(half[M][K]) @ W(half[n][K]) (+bias)(+gelu)
// out: fp16 buffer (cIsHalf) or fp32 buffer (+resid)(+tf32 rnd).
// CTA 128x128, 512 thr, warp 32x32, BK=32, cp.async double-buffered. (R15)
// ============================================================================
__global__ __launch_bounds__(512, 1)
void k_gemm_h(int aId, int K, u64 bOff,
              int cIsHalf, int cId, int ldC,
              const float* __restrict__ bias, int addResid, int gelu, int rnd) {
    __shared__ __align__(16) char Ab[2][8192];
    __shared__ __align__(16) char Bb[2][8192];

    const int tid  = threadIdx.x;
    const int lane = tid & 31;
    const int wid  = tid >> 5;
    const int warp_m = (wid & 3) * 32;
    const int warp_n = (wid >> 2) * 32;
    const int m0 = blockIdx.y * 128;
    const int n0 = blockIdx.x * 128;

    const __half* A = bufh(aId);
    const __half* Bw = g_wtsh + bOff;

    const int kg = tid & 3;
    const int row = tid >> 2;          // 0..127
    const int sw = (kg ^ ((row >> 1) & 3)) << 4;
    const int stOff = row * 64 + sw;

    const __half* aSrc = A + (size_t)(m0 + row) * K + kg * 8;
    const __half* bSrc = Bw + (size_t)(n0 + row) * K + kg * 8;

    const int kb4 = (lane & 3) * 4;

    float c[2][4][4];
#pragma unroll
    for (int i = 0; i < 2; i++)
#pragma unroll
        for (int j = 0; j < 4; j++)
#pragma unroll
            for (int q = 0; q < 4; q++) c[i][j][q] = 0.0f;

    cpa16(smem_u32(Ab[0] + stOff), aSrc);
    cpa16(smem_u32(Bb[0] + stOff), bSrc);
    cpcommit();

    const int iters = K >> 5;
    for (int it = 0; it < iters; it++) {
        cpwait0();
        __syncthreads();
        const int bsel = it & 1;
        const int nsel = bsel ^ 1;
        if (it < iters - 1) {
            int k0 = (it + 1) * 32;
            cpa16(smem_u32(Ab[nsel] + stOff), aSrc + k0);
            cpa16(smem_u32(Bb[nsel] + stOff), bSrc + k0);
            cpcommit();
        }

        const char* Asb = Ab[bsel];
        const char* Bsb = Bb[bsel];
#pragma unroll
        for (int s = 0; s < 2; s++) {
            const int gl0 = s * 2, gl1 = s * 2 + 1;
            uint32_t af[2][4];
#pragma unroll
            for (int ma = 0; ma < 2; ma++) {
                int r0 = warp_m + ma * 16 + (lane >> 2);
                int r1 = r0 + 8;
                int x0 = (r0 >> 1) & 3, x1 = (r1 >> 1) & 3;
                af[ma][0] = *(const uint32_t*)(Asb + r0 * 64 + ((gl0 ^ x0) << 4) + kb4);
                af[ma][1] = *(const uint32_t*)(Asb + r1 * 64 + ((gl0 ^ x1) << 4) + kb4);
                af[ma][2] = *(const uint32_t*)(Asb + r0 * 64 + ((gl1 ^ x0) << 4) + kb4);
                af[ma][3] = *(const uint32_t*)(Asb + r1 * 64 + ((gl1 ^ x1) << 4) + kb4);
            }
#pragma unroll
            for (int na = 0; na < 4; na++) {
                int n = warp_n + na * 8 + (lane >> 2);
                int xn = (n >> 1) & 3;
                uint32_t b0 = *(const uint32_t*)(Bsb + n * 64 + ((gl0 ^ xn) << 4) + kb4);
                uint32_t b1 = *(const uint32_t*)(Bsb + n * 64 + ((gl1 ^ xn) << 4) + kb4);
#pragma unroll
                for (int ma = 0; ma < 2; ma++)
                    mma16(c[ma][na], af[ma], b0, b1);
            }
        }
    }

#pragma unroll
    for (int ma = 0; ma < 2; ma++) {
        int r0 = m0 + warp_m + ma * 16 + (lane >> 2);
        int r1 = r0 + 8;
#pragma unroll
        for (int na = 0; na < 4; na++) {
            int col = n0 + warp_n + na * 8 + (lane & 3) * 2;
            float v[4] = {c[ma][na][0], c[ma][na][1], c[ma][na][2], c[ma][na][3]};
            if (bias) {
                float b0 = bias[col], b1 = bias[col + 1];
                v[0] += b0; v[1] += b1; v[2] += b0; v[3] += b1;
            }
            if (gelu) {
#pragma unroll
                for (int q = 0; q < 4; q++)
                    v[q] = 0.5f * v[q] * (1.0f + erff(v[q] * 0.70710678118654752f));
            }
            if (cIsHalf) {
                __half* Ch = bufh(cId);
                __half2 h0 = __floats2half2_rn(v[0], v[1]);
                __half2 h1 = __floats2half2_rn(v[2], v[3]);
                *(uint32_t*)(Ch + (size_t)r0 * ldC + col) = *(uint32_t*)&h0;
                *(uint32_t*)(Ch + (size_t)r1 * ldC + col) = *(uint32_t*)&h1;
            } else {
                float* C = buf(cId);
                if (addResid) {
                    v[0] += g_x[(size_t)r0 * 512 + col];
                    v[1] += g_x[(size_t)r0 * 512 + col + 1];
                    v[2] += g_x[(size_t)r1 * 512 + col];
                    v[3] += g_x[(size_t)r1 * 512 + col + 1];
                }
                if (rnd) {
#pragma unroll
                    for (int q = 0; q < 4; q++)
                        v[q] = __uint_as_float(f2tf(v[q]));
                }
                *(float2*)(C + (size_t)r0 * ldC + col) = make_float2(v[0], v[1]);
                *(float2*)(C + (size_t)r1 * ldC + col) = make_float2(v[2], v[3]);
            }
        }
    }
}

// ============================================================================
// FUSED attention (FlashAttention-2, tf32 math) — R12/R14 validated;
// only the epilogue changed: writes fp16 g_oh.
// ============================================================================
__global__ __launch_bounds__(256, 1)
void k_attn_fused(const float* __restrict__ tbl, int qkvld, int inner, int hc) {
    extern __shared__ float sm[];
    float* Qs = sm;
    float* Ks = sm + 8192;
    float* Vs = sm + 8192 + 8704;
    float* Ps = sm + 8192 + 8704 + 9216;

    const int tid  = threadIdx.x;
    const int lane = tid & 31;
    const int wid  = tid >> 5;
    const int i0 = blockIdx.x * 128;
    const int z  = blockIdx.y;
    const int bb = z / hc, head = z % hc;
    const float* Qb = g_qkv + (size_t)bb * 1024 * qkvld + head * 64;
    const float* Kb = Qb + inner;
    const float* Vb = Qb + 2 * inner;

    {
        const int aq = tid & 15;
        const int am = tid >> 4;
#pragma unroll
        for (int t = 0; t < 8; t++) {
            int m = am + t * 16;
            float4 v = *(const float4*)(Qb + (size_t)(i0 + m) * qkvld + aq * 4);
            int p = (aq & 8) | ((aq ^ (m & 7)) & 7);
            *(float4*)&Qs[m * 64 + (p << 2)] = v;
        }
    }

    const int rl0 = wid * 16 + (lane >> 2);
    const int rl1 = rl0 + 8;
    const int gr0 = i0 + rl0, gr1 = i0 + rl1;
    const int ih0 = gr0 >> 5, iw0 = gr0 & 31;
    const int ih1 = gr1 >> 5, iw1 = gr1 & 31;
    const int kb  = lane & 3;

    float o[8][4];
#pragma unroll
    for (int j = 0; j < 8; j++) { o[j][0] = o[j][1] = o[j][2] = o[j][3] = 0.f; }
    float m0 = -1e30f, m1 = -1e30f, l0 = 0.f, l1 = 0.f;

    for (int jt = 0; jt < 8; jt++) {
        const int j0 = jt * 128;
        __syncthreads();
        {
            const int n = tid & 127;
            const int cc = tid >> 7;
#pragma unroll
            for (int t = 0; t < 8; t++) {
                int kq = cc + t * 2;
                float4 v = *(const float4*)(Kb + (size_t)(j0 + n) * qkvld + kq * 4);
                Ks[(kq * 4 + 0) * 136 + n] = v.x;
                Ks[(kq * 4 + 1) * 136 + n] = v.y;
                Ks[(kq * 4 + 2) * 136 + n] = v.z;
                Ks[(kq * 4 + 3) * 136 + n] = v.w;
            }
        }
        {
#pragma unroll
            for (int t = 0; t < 8; t++) {
                int idx = tid + t * 256;
                int row = idx >> 4, c4 = idx & 15;
                float4 v = *(const float4*)(Vb + (size_t)(j0 + row) * qkvld + c4 * 4);
                *(float4*)&Vs[row * 72 + c4 * 4] = v;
            }
        }
        __syncthreads();

        float s[16][4];
#pragma unroll
        for (int na = 0; na < 16; na++) { s[na][0] = s[na][1] = s[na][2] = s[na][3] = 0.f; }
#pragma unroll
        for (int kk = 0; kk < 8; kk++) {
            uint32_t af[4];
            int kq0 = kk * 2, kq1 = kk * 2 + 1;
            int p00 = (kq0 & 8) | ((kq0 ^ (rl0 & 7)) & 7);
            int p01 = (kq0 & 8) | ((kq0 ^ (rl1 & 7)) & 7);
            int p10 = (kq1 & 8) | ((kq1 ^ (rl0 & 7)) & 7);
            int p11 = (kq1 & 8) | ((kq1 ^ (rl1 & 7)) & 7);
            af[0] = ldu(&Qs[rl0 * 64 + (p00 << 2) + kb]);
            af[1] = ldu(&Qs[rl1 * 64 + (p01 << 2) + kb]);
            af[2] = ldu(&Qs[rl0 * 64 + (p10 << 2) + kb]);
            af[3] = ldu(&Qs[rl1 * 64 + (p11 << 2) + kb]);
#pragma unroll
            for (int na = 0; na < 16; na++) {
                int n = na * 8 + (lane >> 2);
                uint32_t b0 = ldu(&Ks[(kk * 8 + kb) * 136 + n]);
                uint32_t b1 = ldu(&Ks[(kk * 8 + 4 + kb) * 136 + n]);
                mma8(s[na], af, b0, b1);
            }
        }
#pragma unroll
        for (int na = 0; na < 16; na++) {
            int jj = j0 + na * 8 + (lane & 3) * 2;
            int jh0 = jj >> 5, jw0 = jj & 31;
            int jh1 = (jj + 1) >> 5, jw1 = (jj + 1) & 31;
            s[na][0] = s[na][0] * 0.125f + tbl[(size_t)((ih0 - jh0 + 31) * 63 + (iw0 - jw0 + 31)) * hc + head];
            s[na][1] = s[na][1] * 0.125f + tbl[(size_t)((ih0 - jh1 + 31) * 63 + (iw0 - jw1 + 31)) * hc + head];
            s[na][2] = s[na][2] * 0.125f + tbl[(size_t)((ih1 - jh0 + 31) * 63 + (iw1 - jw0 + 31)) * hc + head];
            s[na][3] = s[na][3] * 0.125f + tbl[(size_t)((ih1 - jh1 + 31) * 63 + (iw1 - jw1 + 31)) * hc + head];
        }
        float mx0 = -1e30f, mx1 = -1e30f;
#pragma unroll
        for (int na = 0; na < 16; na++) {
            mx0 = fmaxf(mx0, fmaxf(s[na][0], s[na][1]));
            mx1 = fmaxf(mx1, fmaxf(s[na][2], s[na][3]));
        }
        mx0 = fmaxf(mx0, __shfl_xor_sync(0xffffffffu, mx0, 1));
        mx0 = fmaxf(mx0, __shfl_xor_sync(0xffffffffu, mx0, 2));
        mx1 = fmaxf(mx1, __shfl_xor_sync(0xffffffffu, mx1, 1));
        mx1 = fmaxf(mx1, __shfl_xor_sync(0xffffffffu, mx1, 2));
        float mn0 = fmaxf(m0, mx0), mn1 = fmaxf(m1, mx1);
        float al0 = __expf(m0 - mn0), al1 = __expf(m1 - mn1);
        float ls0 = 0.f, ls1 = 0.f;
#pragma unroll
        for (int na = 0; na < 16; na++) {
            s[na][0] = __expf(s[na][0] - mn0);
            s[na][1] = __expf(s[na][1] - mn0);
            s[na][2] = __expf(s[na][2] - mn1);
            s[na][3] = __expf(s[na][3] - mn1);
            ls0 += s[na][0] + s[na][1];
            ls1 += s[na][2] + s[na][3];
        }
        ls0 += __shfl_xor_sync(0xffffffffu, ls0, 1);
        ls0 += __shfl_xor_sync(0xffffffffu, ls0, 2);
        ls1 += __shfl_xor_sync(0xffffffffu, ls1, 1);
        ls1 += __shfl_xor_sync(0xffffffffu, ls1, 2);
        l0 = l0 * al0 + ls0;
        l1 = l1 * al1 + ls1;
        m0 = mn0; m1 = mn1;
#pragma unroll
        for (int j = 0; j < 8; j++) {
            o[j][0] *= al0; o[j][1] *= al0; o[j][2] *= al1; o[j][3] *= al1;
        }
#pragma unroll
        for (int na = 0; na < 16; na++) {
            int c = na * 8 + (lane & 3) * 2;
            int g = c >> 2;
            int a0 = rl0 * 128 + ((g ^ (rl0 & 7)) << 2) + (c & 3);
            int a1 = rl1 * 128 + ((g ^ (rl1 & 7)) << 2) + (c & 3);
            Ps[a0]     = __uint_as_float(f2tf(s[na][0]));
            Ps[a0 + 1] = __uint_as_float(f2tf(s[na][1]));
            Ps[a1]     = __uint_as_float(f2tf(s[na][2]));
            Ps[a1 + 1] = __uint_as_float(f2tf(s[na][3]));
        }
        __syncthreads();
#pragma unroll
        for (int kk = 0; kk < 16; kk++) {
            uint32_t af[4];
            int g0 = kk * 2, g1 = kk * 2 + 1;
            af[0] = ldu(&Ps[rl0 * 128 + ((g0 ^ (rl0 & 7)) << 2) + kb]);
            af[1] = ldu(&Ps[rl1 * 128 + ((g0 ^ (rl1 & 7)) << 2) + kb]);
            af[2] = ldu(&Ps[rl0 * 128 + ((g1 ^ (rl0 & 7)) << 2) + kb]);
            af[3] = ldu(&Ps[rl1 * 128 + ((g1 ^ (rl1 & 7)) << 2) + kb]);
#pragma unroll
            for (int na = 0; na < 8; na++) {
                int n = na * 8 + (lane >> 2);
                uint32_t b0 = ldu(&Vs[(kk * 8 + kb) * 72 + n]);
                uint32_t b1 = ldu(&Vs[(kk * 8 + 4 + kb) * 72 + n]);
                mma8(o[na], af, b0, b1);
            }
        }
    }

    // ---- finalize: O / l -> g_oh (fp16) ----
    float inv0 = 1.0f / l0, inv1 = 1.0f / l1;
    __half* Obh = g_oh + ((size_t)bb * 1024) * inner + head * 64;
#pragma unroll
    for (int na = 0; na < 8; na++) {
        int col = na * 8 + (lane & 3) * 2;
        __half2 w0 = __floats2half2_rn(o[na][0] * inv0, o[na][1] * inv0);
        __half2 w1 = __floats2half2_rn(o[na][2] * inv1, o[na][3] * inv1);
        *(uint32_t*)(Obh + (size_t)gr0 * inner + col) = *(uint32_t*)&w0;
        *(uint32_t*)(Obh + (size_t)gr1 * inner + col) = *(uint32_t*)&w1;
    }
}

// ============================================================================
// LayerNorm over 512 — warp-per-row, output fp16 g_xnh
// ============================================================================
__global__ void k_layernorm(const float* __restrict__ s, const float* __restrict__ b) {
    int tid  = threadIdx.x;
    int lane = tid & 31;
    int row  = blockIdx.x * 4 + (tid >> 5);
    const float4* rp = (const float4*)(g_x + (size_t)row * 512);
    float4 v[4];
    float sum = 0.f, sq = 0.f;
#pragma unroll
    for (int q = 0; q < 4; q++) {
        v[q] = rp[lane + 32 * q];
        sum += v[q].x + v[q].y + v[q].z + v[q].w;
        sq  += v[q].x * v[q].x + v[q].y * v[q].y + v[q].z * v[q].z + v[q].w * v[q].w;
    }
#pragma unroll
    for (int o = 16; o; o >>= 1) {
        sum += __shfl_xor_sync(0xffffffffu, sum, o);
        sq  += __shfl_xor_sync(0xffffffffu, sq, o);
    }
    float mean = sum * (1.0f / 512.0f);
    float var  = sq * (1.0f / 512.0f) - mean * mean;
    float rstd = rsqrtf(var + 1e-5f);
#pragma unroll
    for (int q = 0; q < 4; q++) {
        int c4 = lane + 32 * q;
        float4 sv = ((const float4*)s)[c4];
        float4 bv = ((const float4*)b)[c4];
        __half2 h0 = __floats2half2_rn((v[q].x - mean) * rstd * sv.x + bv.x,
                                       (v[q].y - mean) * rstd * sv.y + bv.y);
        __half2 h1 = __floats2half2_rn((v[q].z - mean) * rstd * sv.z + bv.z,
                                       (v[q].w - mean) * rstd * sv.w + bv.w);
        uint2 u; u.x = *(uint32_t*)&h0; u.y = *(uint32_t*)&h1;
        *(uint2*)(g_xnh + (size_t)row * 512 + c4 * 4) = u;
    }
}

// ============================================================================
// final layout: out[b][d][n] = g_x[b][n][d]
// ============================================================================
__global__ void k_out(float* __restrict__ out) {
    __shared__ float t[32][33];
    int bb = blockIdx.z;
    int n0 = blockIdx.x * 32, d0 = blockIdx.y * 32;
    int tx = threadIdx.x, ty = threadIdx.y;
#pragma unroll
    for (int i = 0; i < 32; i += 8)
        t[ty + i][tx] = g_x[((size_t)bb * 1024 + n0 + ty + i) * 512 + d0 + tx];
    __syncthreads();
#pragma unroll
    for (int i = 0; i < 32; i += 8)
        out[((size_t)bb * 512 + d0 + ty + i) * 1024 + n0 + tx] = t[tx][ty + i];
}

// ============================================================================
// host orchestration
// ============================================================================
extern "C" void kernel_launch(void* const* d_in, const int* in_sizes, int n_in,
                              void* d_out, int out_size) {
    const float *img = 0, *patch_w = 0, *patch_b = 0, *pos_emb = 0;
    const float *ln1_s = 0, *ln1_b = 0, *ln2_s = 0, *ln2_b = 0;
    const float *qkv_w[3] = {0, 0, 0}, *out_w[3] = {0, 0, 0}, *out_b[3] = {0, 0, 0};
    const float *tbl[3] = {0, 0, 0};
    const float *ff_w1 = 0, *ff_b1 = 0, *ff_w2 = 0, *ff_b2 = 0;
    int c512 = 0, c1536 = 0, c393 = 0;
    for (int i = 0; i < n_in; i++) {
        const float* p = (const float*)d_in[i];
        switch (in_sizes[i]) {
            case 134217728: img = p; break;
            case 16777216: patch_w = p; break;
            case 524288:   pos_emb = p; break;
            case 512: {
                const float** t[4] = {&patch_b, &out_b[0], &out_b[1], &out_b[2]};
                if (c512 < 4) *t[c512] = p;
                c512++;
            } break;
            case 1536: {
                const float** t[5] = {&ln1_s, &ln1_b, &ln2_s, &ln2_b, &ff_b2};
                if (c1536 < 5) *t[c1536] = p;
                c1536++;
            } break;
            case 768:    ff_b1 = p; break;
            case 196608: qkv_w[0] = p; break;
            case 393216: {
                const float** t[3] = {&qkv_w[1], &ff_w1, &ff_w2};
                if (c393 < 3) *t[c393] = p;
                c393++;
            } break;
            case 786432: qkv_w[2] = p; break;
            case 65536:  out_w[0] = p; break;
            case 131072: out_w[1] = p; break;
            case 262144: out_w[2] = p; break;
            case 7938:   tbl[0] = p; break;
            case 15876:  tbl[1] = p; break;
            case 31752:  tbl[2] = p; break;
            default: break;
        }
    }

    bool ok = img && patch_w && patch_b && pos_emb && ln1_s && ln1_b && ln2_s &&
              ln2_b && ff_w1 && ff_b1 && ff_w2 && ff_b2;
    for (int l = 0; l < 3; l++)
        ok = ok && qkv_w[l] && out_w[l] && out_b[l] && tbl[l];
    if (!ok) {
        k_zero<<<(out_size + 255) / 256, 256>>>((float*)d_out, out_size);
        return;
    }

    const int PATCH_SMEM = 32768 + 16384;                    // 49152 B
    const int ATT_SMEM   = (8192 + 8704 + 9216 + 16384) * 4; // 169984 B
    cudaFuncSetAttribute(k_patch_h,
                         cudaFuncAttributeMaxDynamicSharedMemorySize, PATCH_SMEM);
    cudaFuncSetAttribute(k_attn_fused,
                         cudaFuncAttributeMaxDynamicSharedMemorySize, ATT_SMEM);

    k_permute_pw<<<(4096 * 512 + 255) / 256, 256>>>(patch_w);
    k_patch_h<<<dim3(4, 16, 2), 256, PATCH_SMEM>>>(img);
    k_patch_sum<<<(4096 * 128 + 255) / 256, 256>>>(patch_b, pos_emb);

    // ---- all weights -> fp16 [n][K] g_wtsh (ONE launch, 12 segments) ----
    const u64 QKVH_OFF[3] = {0ULL, 196608ULL, 589824ULL};
    const u64 FF1H_OFF = 1376256ULL;   // + l*131072
    const u64 FF2H_OFF = 1769472ULL;   // + l*131072
    const u64 OUTH_OFF[3] = {2162688ULL, 2228224ULL, 2359296ULL};
    {
        TJobs j;
        const float* srcs[12] = {qkv_w[0], qkv_w[1], qkv_w[2],
                                 ff_w1, ff_w1 + 131072, ff_w1 + 262144,
                                 ff_w2, ff_w2 + 131072, ff_w2 + 262144,
                                 out_w[0], out_w[1], out_w[2]};
        u64 dsts[12] = {QKVH_OFF[0], QKVH_OFF[1], QKVH_OFF[2],
                        FF1H_OFF, FF1H_OFF + 131072, FF1H_OFF + 262144,
                        FF2H_OFF, FF2H_OFF + 131072, FF2H_OFF + 262144,
                        OUTH_OFF[0], OUTH_OFF[1], OUTH_OFF[2]};
        int Ks[12] = {512, 512, 512, 512, 512, 512, 256, 256, 256, 128, 256, 512};
        int Ns[12] = {384, 768, 1536, 256, 256, 256, 512, 512, 512, 512, 512, 512};
        int cum = 0;
        for (int i = 0; i < 12; i++) {
            j.src[i] = srcs[i]; j.dst[i] = dsts[i];
            j.K[i] = Ks[i]; j.N[i] = Ns[i]; j.cum[i] = cum;
            cum += (Ks[i] >> 3) * Ns[i];
        }
        j.cum[12] = cum;
        k_cvt_t_all<<<(cum + 255) / 256, 256>>>(j);
    }

    const int heads[3] = {2, 4, 8};
    for (int l = 0; l < 3; l++) {
        int h = heads[l];
        int inner = 64 * h;
        int qkvld = 3 * inner;

        // ---- attention ----
        k_layernorm<<<1024, 128>>>(ln1_s + l * 512, ln1_b + l * 512);
        k_gemm_h<<<dim3(qkvld / 128, 32), 512>>>(
            HBUF_XN, 512, QKVH_OFF[l], 0, BUF_QKV, qkvld, nullptr, 0, 0, 1);
        k_attn_fused<<<dim3(8, 4 * h), 256, ATT_SMEM>>>(tbl[l], qkvld, inner, h);
        k_gemm_h<<<dim3(4, 32), 512>>>(
            HBUF_O, inner, OUTH_OFF[l], 0, BUF_X, 512, out_b[l], 1, 0, 0);

        // ---- feed-forward ----
        k_layernorm<<<1024, 128>>>(ln2_s + l * 512, ln2_b + l * 512);
        k_gemm_h<<<dim3(2, 32), 512>>>(
            HBUF_XN, 512, FF1H_OFF + (u64)l * 131072, 1, HBUF_H, 256,
            ff_b1 + l * 256, 0, 1, 0);
        k_gemm_h<<<dim3(4, 32), 512>>>(
            HBUF_H, 256, FF2H_OFF + (u64)l * 131072, 0, BUF_X, 512,
            ff_b2 + l * 512, 1, 0, 0);
    }

    k_out<<<dim3(32, 16, 4), dim3(32, 8)>>>((float*)d_out);
}